// round 11
// baseline (speedup 1.0000x reference)
#include <cuda_runtime.h>
#include <cuda_fp16.h>

// ===== static scratch (allocation-free rule: __device__ globals) =====
#define N_MAX 100352
#define E_MAX 1700032

__device__ int   g_cnt[N_MAX];       // zero at load; self-cleaned by k_a2 each run
__device__ int   g_fill[N_MAX];
__device__ int   g_off[N_MAX + 1];
__device__ int   g_bsum[1024];
__device__ float g_dinv[N_MAX];
__device__ float g_a1f[N_MAX];       // atomic accum of sum dinv[src]; self-cleaned by k_a2
__device__ int   g_src[E_MAX];       // CSR src indices (weightless)

__device__ float g_a1[N_MAX];        // P·1
__device__ float g_at[N_MAX];        // dinv * a1
__device__ float g_a2[N_MAX];        // P²·1
__device__ float g_U[96 * 64];       // [W1@W3_top ; W2@W3_bot]
__device__ float g_c4[64];           // ([b1|b2]@W3)@W4
__device__ float g_e4[64];           // b3@W4
__device__ float g_f4[64];           // b4

__device__ __align__(16) __half g_T0[(size_t)N_MAX * 64];  // V, then Dinv·V (in place)
__device__ __align__(16) __half g_T1[(size_t)N_MAX * 64];
__device__ __align__(16) __half g_T2[(size_t)N_MAX * 64];
__device__ float                g_Y3[(size_t)N_MAX * 64];  // P³V

// ===== packed fp32x2 helpers (sm_103a) =====
__device__ __forceinline__ unsigned long long ffma2(unsigned long long a,
                                                    unsigned long long b,
                                                    unsigned long long c) {
    unsigned long long d;
    asm("fma.rn.f32x2 %0, %1, %2, %3;" : "=l"(d) : "l"(a), "l"(b), "l"(c));
    return d;
}
__device__ __forceinline__ unsigned long long pack2(float x) {
    unsigned long long d;
    asm("mov.b64 %0, {%1, %1};" : "=l"(d) : "r"(__float_as_uint(x)));
    return d;
}
__device__ __forceinline__ float2 unpack2(unsigned long long v) {
    unsigned int lo, hi;
    asm("mov.b64 {%0, %1}, %2;" : "=r"(lo), "=r"(hi) : "l"(v));
    return make_float2(__uint_as_float(lo), __uint_as_float(hi));
}

// ============================ graph construction ============================

// 4 edges per thread for MLP on the atomics
__global__ void k_hist(const int* __restrict__ col, int E) {
    int e = (blockIdx.x * blockDim.x + threadIdx.x) * 4;
    if (e + 4 <= E) {
        int4 c = *reinterpret_cast<const int4*>(col + e);
        atomicAdd(&g_cnt[c.x], 1);
        atomicAdd(&g_cnt[c.y], 1);
        atomicAdd(&g_cnt[c.z], 1);
        atomicAdd(&g_cnt[c.w], 1);
    } else {
        for (; e < E; e++) atomicAdd(&g_cnt[col[e]], 1);
    }
}

__global__ void __launch_bounds__(1024) k_scan_local(int n) {
    __shared__ int s[1024];
    int tid = threadIdx.x;
    int i = blockIdx.x * 1024 + tid;
    int v = (i < n) ? g_cnt[i] : 0;
    s[tid] = v;
    __syncthreads();
    for (int d = 1; d < 1024; d <<= 1) {
        int t = (tid >= d) ? s[tid - d] : 0;
        __syncthreads();
        s[tid] += t;
        __syncthreads();
    }
    if (i < n) g_off[i] = s[tid] - v;
    if (tid == 1023) g_bsum[blockIdx.x] = s[1023];
}

// merged: every block re-scans the <=128 per-block sums in smem, then finalizes.
__global__ void __launch_bounds__(256) k_scan_add(int n, int E, int nb) {
    __shared__ int sb[128];
    int tid = threadIdx.x;
    if (tid < 128) sb[tid] = (tid < nb) ? g_bsum[tid] : 0;
    __syncthreads();
    for (int d = 1; d < 128; d <<= 1) {
        int t = (tid >= d && tid < 128) ? sb[tid - d] : 0;
        __syncthreads();
        if (tid < 128) sb[tid] += t;   // inclusive scan
        __syncthreads();
    }
    int i = blockIdx.x * blockDim.x + tid;
    if (i < n) {
        int b = i >> 10;
        int pre = b ? sb[b - 1] : 0;
        int o = g_off[i] + pre;
        g_off[i]  = o;
        g_fill[i] = o;
        g_dinv[i] = rsqrtf((float)(g_cnt[i] + 1));
    }
    if (i == n) g_off[n] = E;
}

// fill CSR src; accumulate a1f[c] += dinv[r].  4 edges per thread for MLP.
__global__ void k_fill(const int* __restrict__ row, const int* __restrict__ col, int E) {
    int e = (blockIdx.x * blockDim.x + threadIdx.x) * 4;
    if (e + 4 <= E) {
        int4 r = *reinterpret_cast<const int4*>(row + e);
        int4 c = *reinterpret_cast<const int4*>(col + e);
        float d0 = g_dinv[r.x], d1 = g_dinv[r.y], d2 = g_dinv[r.z], d3 = g_dinv[r.w];
        int p0 = atomicAdd(&g_fill[c.x], 1);
        int p1 = atomicAdd(&g_fill[c.y], 1);
        int p2 = atomicAdd(&g_fill[c.z], 1);
        int p3 = atomicAdd(&g_fill[c.w], 1);
        g_src[p0] = r.x; g_src[p1] = r.y; g_src[p2] = r.z; g_src[p3] = r.w;
        atomicAdd(&g_a1f[c.x], d0);
        atomicAdd(&g_a1f[c.y], d1);
        atomicAdd(&g_a1f[c.z], d2);
        atomicAdd(&g_a1f[c.w], d3);
    } else {
        for (; e < E; e++) {
            int r = row[e], c = col[e];
            int pos = atomicAdd(&g_fill[c], 1);
            g_src[pos] = r;
            atomicAdd(&g_a1f[c], g_dinv[r]);
        }
    }
}

// ============================ weight precompute (parallel, side stream) ============================
__global__ void __launch_bounds__(256) k_wprep2(
        const float* __restrict__ W1, const float* __restrict__ W2,
        const float* __restrict__ W3, const float* __restrict__ W4,
        const float* __restrict__ b1, const float* __restrict__ b2,
        const float* __restrict__ b3, const float* __restrict__ b4) {
    int tid = threadIdx.x;
    int b = blockIdx.x;
    if (b < 24) {
        __shared__ float sB[64 * 64];
        __shared__ float sA[4 * 64];
        int k0 = b * 4;
        int half = (k0 >= 64);
        const float* Wsrc = W3 + (size_t)half * 64 * 64;
        for (int i = tid; i < 64 * 64; i += 256) sB[i] = Wsrc[i];
        const float* Arow = half ? (W2 + (size_t)(k0 - 64) * 64) : (W1 + (size_t)k0 * 64);
        sA[tid] = Arow[tid];
        __syncthreads();
        int k = tid >> 6, j = tid & 63;
        float s = 0.f;
#pragma unroll
        for (int m = 0; m < 64; m++) s += sA[k * 64 + m] * sB[m * 64 + j];
        g_U[(k0 + k) * 64 + j] = s;
    } else {
        __shared__ float c3[64];
        int j = tid & 63;
        if (tid < 64) {
            float s = 0.f;
            for (int m = 0; m < 128; m++)
                s += ((m < 64) ? b1[m] : b2[m - 64]) * W3[m * 64 + j];
            c3[j] = s;
        }
        __syncthreads();
        if (tid < 64) {
            float s = 0.f, t = 0.f;
            for (int m = 0; m < 64; m++) {
                s += c3[m] * W4[m * 64 + j];
                t += b3[m] * W4[m * 64 + j];
            }
            g_c4[j] = s; g_e4[j] = t; g_f4[j] = b4[j];
        }
    }
}

// ============================ gemm0v: V = [L|C]@U (fp16, unscaled; side stream) ============================
__global__ void __launch_bounds__(256) k_gemm0v(const float* __restrict__ latent,
                                                const float* __restrict__ cond, int n) {
    __shared__ __align__(16) float sW[96 * 64];
    for (int i = threadIdx.x; i < 96 * 64; i += blockDim.x) sW[i] = g_U[i];
    __syncthreads();
    int node = blockIdx.x * blockDim.x + threadIdx.x;
    if (node >= n) return;

    unsigned long long acc[32];
#pragma unroll
    for (int j = 0; j < 32; j++) acc[j] = 0ull;

    const float* pL = latent + (size_t)node * 64;
    const float* pC = cond   + (size_t)node * 32;
#pragma unroll 2
    for (int k = 0; k < 96; k += 4) {
        float4 av = (k < 64) ? *reinterpret_cast<const float4*>(pL + k)
                             : *reinterpret_cast<const float4*>(pC + (k - 64));
        unsigned long long p0 = pack2(av.x), p1 = pack2(av.y);
        unsigned long long p2 = pack2(av.z), p3 = pack2(av.w);
        const ulonglong2* w0 = reinterpret_cast<const ulonglong2*>(sW + (k + 0) * 64);
        const ulonglong2* w1 = reinterpret_cast<const ulonglong2*>(sW + (k + 1) * 64);
        const ulonglong2* w2 = reinterpret_cast<const ulonglong2*>(sW + (k + 2) * 64);
        const ulonglong2* w3 = reinterpret_cast<const ulonglong2*>(sW + (k + 3) * 64);
#pragma unroll
        for (int j = 0; j < 16; j++) {
            ulonglong2 q;
            q = w0[j]; acc[2*j] = ffma2(p0, q.x, acc[2*j]); acc[2*j+1] = ffma2(p0, q.y, acc[2*j+1]);
            q = w1[j]; acc[2*j] = ffma2(p1, q.x, acc[2*j]); acc[2*j+1] = ffma2(p1, q.y, acc[2*j+1]);
            q = w2[j]; acc[2*j] = ffma2(p2, q.x, acc[2*j]); acc[2*j+1] = ffma2(p2, q.y, acc[2*j+1]);
            q = w3[j]; acc[2*j] = ffma2(p3, q.x, acc[2*j]); acc[2*j+1] = ffma2(p3, q.y, acc[2*j+1]);
        }
    }

    __half* yp = g_T0 + (size_t)node * 64;
#pragma unroll
    for (int j = 0; j < 8; j++) {
        float2 f0 = unpack2(acc[4*j+0]);
        float2 f1 = unpack2(acc[4*j+1]);
        float2 f2 = unpack2(acc[4*j+2]);
        float2 f3 = unpack2(acc[4*j+3]);
        __half2 h0 = __floats2half2_rn(f0.x, f0.y);
        __half2 h1 = __floats2half2_rn(f1.x, f1.y);
        __half2 h2 = __floats2half2_rn(f2.x, f2.y);
        __half2 h3 = __floats2half2_rn(f3.x, f3.y);
        uint4 u = make_uint4(*reinterpret_cast<unsigned*>(&h0), *reinterpret_cast<unsigned*>(&h1),
                             *reinterpret_cast<unsigned*>(&h2), *reinterpret_cast<unsigned*>(&h3));
        *reinterpret_cast<uint4*>(yp + 8 * j) = u;
    }
}

// ============================ scale: T0 *= dinv (in place; side stream, overlaps fill) ============================
__global__ void k_scale(int n) {
    int idx = blockIdx.x * blockDim.x + threadIdx.x;
    if (idx >= n * 8) return;
    int node = idx >> 3;
    int c = (idx & 7) * 8;
    float dn = g_dinv[node];
    __half* p = g_T0 + (size_t)node * 64 + c;
    uint4 u = *reinterpret_cast<uint4*>(p);
    __half2* h = reinterpret_cast<__half2*>(&u);
#pragma unroll
    for (int q = 0; q < 4; q++) {
        float2 f = __half22float2(h[q]);
        h[q] = __floats2half2_rn(f.x * dn, f.y * dn);
    }
    *reinterpret_cast<uint4*>(p) = u;
}

// a2 = P·a1 (side stream, overlaps agg2/agg3); also self-cleans cnt & a1f for next run
__global__ void k_a2(int n) {
    int wid  = (blockIdx.x * blockDim.x + threadIdx.x) >> 5;
    int lane = threadIdx.x & 31;
    if (wid >= n) return;
    int beg = g_off[wid], end = g_off[wid + 1];
    float acc = 0.f;
    for (int e = beg + lane; e < end; e += 32) acc += g_at[g_src[e]];
    for (int d = 16; d; d >>= 1) acc += __shfl_down_sync(0xffffffffu, acc, d);
    if (lane == 0) g_a2[wid] = g_dinv[wid] * (acc + g_at[wid]);
    if (lane == 1) g_cnt[wid] = 0;     // self-clean for next replay
    if (lane == 2) g_a1f[wid] = 0.f;
}

// ============================ weightless aggregation (uint4 gather, 4 edges/warp-instr) ============================
// Warp lanes: g = lane>>3 picks edge slot (0..3), sub = lane&7 picks 16B chunk of row.
// acc[8] per lane covers features sub*8 .. sub*8+7 for its edge group; reduced across
// groups with 2 shfl_xor rounds.  MODE 0: fp16 out (dinv²), MODE 1: fp32 out (dinv).
template <int MODE, bool FIRST>
__global__ void __launch_bounds__(256) k_aggp(const __half* __restrict__ X,
                                              void* __restrict__ Yv, int n) {
    int wid  = (blockIdx.x * blockDim.x + threadIdx.x) >> 5;
    int lane = threadIdx.x & 31;
    if (wid >= n) return;
    const int g   = lane >> 3;
    const int sub = lane & 7;

    int e = g_off[wid];
    const int end = g_off[wid + 1];
    float acc[8];
#pragma unroll
    for (int k = 0; k < 8; k++) acc[k] = 0.f;

#define ACCUM(V) { const __half2* hh = reinterpret_cast<const __half2*>(&(V));            \
                   _Pragma("unroll")                                                      \
                   for (int q = 0; q < 4; q++) {                                          \
                       float2 f = __half22float2(hh[q]);                                  \
                       acc[2*q] += f.x; acc[2*q+1] += f.y; } }

    // 8 edges per iteration: two uint4 gathers in flight per lane
    for (; e + 8 <= end; e += 8) {
        int s0 = g_src[e + g];
        int s1 = g_src[e + 4 + g];
        uint4 v0 = *reinterpret_cast<const uint4*>(X + (size_t)s0 * 64 + sub * 8);
        uint4 v1 = *reinterpret_cast<const uint4*>(X + (size_t)s1 * 64 + sub * 8);
        ACCUM(v0) ACCUM(v1)
    }
    for (; e + 4 <= end; e += 4) {
        int s0 = g_src[e + g];
        uint4 v0 = *reinterpret_cast<const uint4*>(X + (size_t)s0 * 64 + sub * 8);
        ACCUM(v0)
    }
    {   // tail: r (<4) remaining edges + self loop = r+1 (<=4) items
        int r = end - e;
        int s = (g < r) ? g_src[e + g] : ((g == r) ? wid : -1);
        if (s >= 0) {
            uint4 v0 = *reinterpret_cast<const uint4*>(X + (size_t)s * 64 + sub * 8);
            ACCUM(v0)
        }
    }
#undef ACCUM

    // reduce across the 4 edge groups (lanes sub, sub+8, sub+16, sub+24)
#pragma unroll
    for (int k = 0; k < 8; k++) {
        acc[k] += __shfl_xor_sync(0xffffffffu, acc[k], 8);
        acc[k] += __shfl_xor_sync(0xffffffffu, acc[k], 16);
    }

    float dn = g_dinv[wid];
    if (FIRST && lane == 0) {
        float a1 = dn * (g_a1f[wid] + dn);
        g_a1[wid] = a1;
        g_at[wid] = dn * a1;
    }
    if (lane < 8) {
        if (MODE == 0) {
            float s = dn * dn;
            uint4 u;
            __half2* h = reinterpret_cast<__half2*>(&u);
#pragma unroll
            for (int q = 0; q < 4; q++)
                h[q] = __floats2half2_rn(acc[2*q] * s, acc[2*q+1] * s);
            *reinterpret_cast<uint4*>((__half*)Yv + (size_t)wid * 64 + sub * 8) = u;
        } else {
            float* yp = (float*)Yv + (size_t)wid * 64 + sub * 8;
            *reinterpret_cast<float4*>(yp) =
                make_float4(acc[0] * dn, acc[1] * dn, acc[2] * dn, acc[3] * dn);
            *reinterpret_cast<float4*>(yp + 4) =
                make_float4(acc[4] * dn, acc[5] * dn, acc[6] * dn, acc[7] * dn);
        }
    }
}

// ============================ final GEMM ============================
__global__ void __launch_bounds__(256) k_gemm_final(const float* __restrict__ A,
                                                    const float* __restrict__ Wg,
                                                    float* __restrict__ Y, int n) {
    __shared__ __align__(16) float sW[64 * 64];
    __shared__ float sc[64], se[64], sf[64];
    for (int i = threadIdx.x; i < 64 * 64; i += blockDim.x) sW[i] = Wg[i];
    if (threadIdx.x < 64) {
        sc[threadIdx.x] = g_c4[threadIdx.x];
        se[threadIdx.x] = g_e4[threadIdx.x];
        sf[threadIdx.x] = g_f4[threadIdx.x];
    }
    __syncthreads();
    int node = blockIdx.x * blockDim.x + threadIdx.x;
    if (node >= n) return;

    unsigned long long acc[32];
#pragma unroll
    for (int j = 0; j < 32; j++) acc[j] = 0ull;

    const float* arow = A + (size_t)node * 64;
#pragma unroll 2
    for (int k = 0; k < 64; k += 4) {
        float4 av = *reinterpret_cast<const float4*>(arow + k);
        unsigned long long p0 = pack2(av.x), p1 = pack2(av.y);
        unsigned long long p2 = pack2(av.z), p3 = pack2(av.w);
        const ulonglong2* w0 = reinterpret_cast<const ulonglong2*>(sW + (k + 0) * 64);
        const ulonglong2* w1 = reinterpret_cast<const ulonglong2*>(sW + (k + 1) * 64);
        const ulonglong2* w2 = reinterpret_cast<const ulonglong2*>(sW + (k + 2) * 64);
        const ulonglong2* w3 = reinterpret_cast<const ulonglong2*>(sW + (k + 3) * 64);
#pragma unroll
        for (int j = 0; j < 16; j++) {
            ulonglong2 q;
            q = w0[j]; acc[2*j] = ffma2(p0, q.x, acc[2*j]); acc[2*j+1] = ffma2(p0, q.y, acc[2*j+1]);
            q = w1[j]; acc[2*j] = ffma2(p1, q.x, acc[2*j]); acc[2*j+1] = ffma2(p1, q.y, acc[2*j+1]);
            q = w2[j]; acc[2*j] = ffma2(p2, q.x, acc[2*j]); acc[2*j+1] = ffma2(p2, q.y, acc[2*j+1]);
            q = w3[j]; acc[2*j] = ffma2(p3, q.x, acc[2*j]); acc[2*j+1] = ffma2(p3, q.y, acc[2*j+1]);
        }
    }

    float av1 = g_a1[node], av2 = g_a2[node];
    float* yrow = Y + (size_t)node * 64;
#pragma unroll
    for (int j = 0; j < 16; j++) {
        float2 lo = unpack2(acc[2*j]);
        float2 hi = unpack2(acc[2*j+1]);
        int c0 = 4 * j;
        float4 o;
        o.x = lo.x + av2 * sc[c0+0] + av1 * se[c0+0] + sf[c0+0];
        o.y = lo.y + av2 * sc[c0+1] + av1 * se[c0+1] + sf[c0+1];
        o.z = hi.x + av2 * sc[c0+2] + av1 * se[c0+2] + sf[c0+2];
        o.w = hi.y + av2 * sc[c0+3] + av1 * se[c0+3] + sf[c0+3];
        *reinterpret_cast<float4*>(yrow + c0) = o;
    }
}

// ============================ launch ============================

extern "C" void kernel_launch(void* const* d_in, const int* in_sizes, int n_in,
                              void* d_out, int out_size) {
    const float* latent = (const float*)d_in[0];
    const float* cond   = (const float*)d_in[1];
    const int*   edge   = (const int*)  d_in[2];
    const float* W1 = (const float*)d_in[3];
    const float* b1 = (const float*)d_in[4];
    const float* W2 = (const float*)d_in[5];
    const float* b2 = (const float*)d_in[6];
    const float* W3 = (const float*)d_in[7];
    const float* b3 = (const float*)d_in[8];
    const float* W4 = (const float*)d_in[9];
    const float* b4 = (const float*)d_in[10];

    const int n = in_sizes[0] / 64;      // 100000
    const int E = in_sizes[2] / 2;       // 1600000
    const int* row = edge;
    const int* col = edge + E;

    static __half *pT0 = nullptr, *pT1 = nullptr, *pT2 = nullptr;
    static float *pY3 = nullptr;
    static cudaStream_t sB = nullptr;
    static cudaEvent_t ev0 = nullptr, evAdd = nullptr, evScale = nullptr,
                       evAgg1 = nullptr, evA2 = nullptr;
    if (!pT0) {
        cudaGetSymbolAddress((void**)&pT0,  g_T0);
        cudaGetSymbolAddress((void**)&pT1,  g_T1);
        cudaGetSymbolAddress((void**)&pT2,  g_T2);
        cudaGetSymbolAddress((void**)&pY3,  g_Y3);
        cudaStreamCreateWithFlags(&sB, cudaStreamNonBlocking);
        cudaEventCreateWithFlags(&ev0,     cudaEventDisableTiming);
        cudaEventCreateWithFlags(&evAdd,   cudaEventDisableTiming);
        cudaEventCreateWithFlags(&evScale, cudaEventDisableTiming);
        cudaEventCreateWithFlags(&evAgg1,  cudaEventDisableTiming);
        cudaEventCreateWithFlags(&evA2,    cudaEventDisableTiming);
    }

    const int TB  = 256;
    const int gN  = (n + TB - 1) / TB;
    const int gE4 = ((E + 3) / 4 + TB - 1) / TB;   // 4 edges per thread
    const int nbS = (n + 1023) / 1024;             // <= 98 <= 128
    const int gN1 = (n + 1 + TB - 1) / TB;
    const int gW  = (n + 7) / 8;                   // warp per node, 8 warps/block
    const int gS  = (n * 8 + TB - 1) / TB;         // scale kernel

    // ---- fork: side stream B handles the weight path ----
    cudaEventRecord(ev0, 0);
    cudaStreamWaitEvent(sB, ev0, 0);
    k_wprep2<<<25, 256, 0, sB>>>(W1, W2, W3, W4, b1, b2, b3, b4);
    k_gemm0v<<<gN, TB, 0, sB>>>(latent, cond, n);   // V = [L|C]@U (unscaled)

    // ---- main stream: edge/build chain (no memset — cnt/a1f self-cleaned) ----
    k_hist<<<gE4, TB>>>(col, E);
    k_scan_local<<<nbS, 1024>>>(n);
    k_scan_add<<<gN1, TB>>>(n, E, nbS);
    cudaEventRecord(evAdd, 0);
    k_fill<<<gE4, TB>>>(row, col, E);

    // ---- side stream: scale T0 by dinv (needs scan_add + gemm0v), overlaps fill ----
    cudaStreamWaitEvent(sB, evAdd, 0);
    k_scale<<<gS, TB, 0, sB>>>(n);
    cudaEventRecord(evScale, sB);

    // ---- main stream: agg1 (finalizes a1/at), agg2, agg3 ----
    cudaStreamWaitEvent(0, evScale, 0);
    k_aggp<0, true ><<<gW, TB>>>(pT0, pT1, n);
    cudaEventRecord(evAgg1, 0);
    k_aggp<0, false><<<gW, TB>>>(pT1, pT2, n);
    k_aggp<1, false><<<gW, TB>>>(pT2, pY3, n);

    // ---- side stream: a2 gather (needs agg1's a1/at), overlaps agg2/agg3 ----
    cudaStreamWaitEvent(sB, evAgg1, 0);
    k_a2<<<gW, TB, 0, sB>>>(n);
    cudaEventRecord(evA2, sB);

    // ---- out = Y3@W4 + a2·c4 + a1·e4 + f4 ----
    cudaStreamWaitEvent(0, evA2, 0);
    k_gemm_final<<<gN, TB>>>(pY3, W4, (float*)d_out, n);
}

// round 12
// speedup vs baseline: 1.0174x; 1.0174x over previous
#include <cuda_runtime.h>
#include <cuda_fp16.h>

// ===== static scratch (allocation-free rule: __device__ globals) =====
#define N_MAX 100352
#define BUCKET 96

__device__ int   g_fill[N_MAX];                 // degree counters; zero at load; cleaned by gemm_final
__device__ float g_dinv[N_MAX];
__device__ int   g_src[(size_t)N_MAX * BUCKET]; // bucketed adjacency (src per dest)

__device__ float g_a1[N_MAX];        // P·1
__device__ float g_at[N_MAX];        // dinv * a1
__device__ float g_a2[N_MAX];        // P²·1
__device__ float g_U[96 * 64];       // [W1@W3_top ; W2@W3_bot]
__device__ float g_c4[64];           // ([b1|b2]@W3)@W4
__device__ float g_e4[64];           // b3@W4
__device__ float g_f4[64];           // b4

__device__ __align__(16) __half g_T0[(size_t)N_MAX * 64];  // V, then Dinv·V (in place)
__device__ __align__(16) __half g_T1[(size_t)N_MAX * 64];
__device__ __align__(16) __half g_T2[(size_t)N_MAX * 64];
__device__ float                g_Y3[(size_t)N_MAX * 64];  // P³V

// ===== packed fp32x2 helpers (sm_103a) =====
__device__ __forceinline__ unsigned long long ffma2(unsigned long long a,
                                                    unsigned long long b,
                                                    unsigned long long c) {
    unsigned long long d;
    asm("fma.rn.f32x2 %0, %1, %2, %3;" : "=l"(d) : "l"(a), "l"(b), "l"(c));
    return d;
}
__device__ __forceinline__ unsigned long long pack2(float x) {
    unsigned long long d;
    asm("mov.b64 %0, {%1, %1};" : "=l"(d) : "r"(__float_as_uint(x)));
    return d;
}
__device__ __forceinline__ float2 unpack2(unsigned long long v) {
    unsigned int lo, hi;
    asm("mov.b64 {%0, %1}, %2;" : "=r"(lo), "=r"(hi) : "l"(v));
    return make_float2(__uint_as_float(lo), __uint_as_float(hi));
}

// ============================ bucketed fill (no hist, no scan) ============================

__global__ void k_fill(const int* __restrict__ row, const int* __restrict__ col, int E) {
    int e = blockIdx.x * blockDim.x + threadIdx.x;
    if (e < E) {
        int r = row[e], c = col[e];
        int pos = atomicAdd(&g_fill[c], 1);
        if (pos < BUCKET) g_src[(size_t)c * BUCKET + pos] = r;
    }
}

// ============================ weight precompute (parallel, side stream) ============================
__global__ void __launch_bounds__(256) k_wprep2(
        const float* __restrict__ W1, const float* __restrict__ W2,
        const float* __restrict__ W3, const float* __restrict__ W4,
        const float* __restrict__ b1, const float* __restrict__ b2,
        const float* __restrict__ b3, const float* __restrict__ b4) {
    int tid = threadIdx.x;
    int b = blockIdx.x;
    if (b < 24) {
        __shared__ float sB[64 * 64];
        __shared__ float sA[4 * 64];
        int k0 = b * 4;
        int half = (k0 >= 64);
        const float* Wsrc = W3 + (size_t)half * 64 * 64;
        for (int i = tid; i < 64 * 64; i += 256) sB[i] = Wsrc[i];
        const float* Arow = half ? (W2 + (size_t)(k0 - 64) * 64) : (W1 + (size_t)k0 * 64);
        sA[tid] = Arow[tid];
        __syncthreads();
        int k = tid >> 6, j = tid & 63;
        float s = 0.f;
#pragma unroll
        for (int m = 0; m < 64; m++) s += sA[k * 64 + m] * sB[m * 64 + j];
        g_U[(k0 + k) * 64 + j] = s;
    } else {
        __shared__ float c3[64];
        int j = tid & 63;
        if (tid < 64) {
            float s = 0.f;
            for (int m = 0; m < 128; m++)
                s += ((m < 64) ? b1[m] : b2[m - 64]) * W3[m * 64 + j];
            c3[j] = s;
        }
        __syncthreads();
        if (tid < 64) {
            float s = 0.f, t = 0.f;
            for (int m = 0; m < 64; m++) {
                s += c3[m] * W4[m * 64 + j];
                t += b3[m] * W4[m * 64 + j];
            }
            g_c4[j] = s; g_e4[j] = t; g_f4[j] = b4[j];
        }
    }
}

// ============================ gemm0v: V = [L|C]@U (fp16, unscaled; side stream) ============================
__global__ void __launch_bounds__(256) k_gemm0v(const float* __restrict__ latent,
                                                const float* __restrict__ cond, int n) {
    __shared__ __align__(16) float sW[96 * 64];
    for (int i = threadIdx.x; i < 96 * 64; i += blockDim.x) sW[i] = g_U[i];
    __syncthreads();
    int node = blockIdx.x * blockDim.x + threadIdx.x;
    if (node >= n) return;

    unsigned long long acc[32];
#pragma unroll
    for (int j = 0; j < 32; j++) acc[j] = 0ull;

    const float* pL = latent + (size_t)node * 64;
    const float* pC = cond   + (size_t)node * 32;
#pragma unroll 2
    for (int k = 0; k < 96; k += 4) {
        float4 av = (k < 64) ? *reinterpret_cast<const float4*>(pL + k)
                             : *reinterpret_cast<const float4*>(pC + (k - 64));
        unsigned long long p0 = pack2(av.x), p1 = pack2(av.y);
        unsigned long long p2 = pack2(av.z), p3 = pack2(av.w);
        const ulonglong2* w0 = reinterpret_cast<const ulonglong2*>(sW + (k + 0) * 64);
        const ulonglong2* w1 = reinterpret_cast<const ulonglong2*>(sW + (k + 1) * 64);
        const ulonglong2* w2 = reinterpret_cast<const ulonglong2*>(sW + (k + 2) * 64);
        const ulonglong2* w3 = reinterpret_cast<const ulonglong2*>(sW + (k + 3) * 64);
#pragma unroll
        for (int j = 0; j < 16; j++) {
            ulonglong2 q;
            q = w0[j]; acc[2*j] = ffma2(p0, q.x, acc[2*j]); acc[2*j+1] = ffma2(p0, q.y, acc[2*j+1]);
            q = w1[j]; acc[2*j] = ffma2(p1, q.x, acc[2*j]); acc[2*j+1] = ffma2(p1, q.y, acc[2*j+1]);
            q = w2[j]; acc[2*j] = ffma2(p2, q.x, acc[2*j]); acc[2*j+1] = ffma2(p2, q.y, acc[2*j+1]);
            q = w3[j]; acc[2*j] = ffma2(p3, q.x, acc[2*j]); acc[2*j+1] = ffma2(p3, q.y, acc[2*j+1]);
        }
    }

    __half* yp = g_T0 + (size_t)node * 64;
#pragma unroll
    for (int j = 0; j < 8; j++) {
        float2 f0 = unpack2(acc[4*j+0]);
        float2 f1 = unpack2(acc[4*j+1]);
        float2 f2 = unpack2(acc[4*j+2]);
        float2 f3 = unpack2(acc[4*j+3]);
        __half2 h0 = __floats2half2_rn(f0.x, f0.y);
        __half2 h1 = __floats2half2_rn(f1.x, f1.y);
        __half2 h2 = __floats2half2_rn(f2.x, f2.y);
        __half2 h3 = __floats2half2_rn(f3.x, f3.y);
        uint4 u = make_uint4(*reinterpret_cast<unsigned*>(&h0), *reinterpret_cast<unsigned*>(&h1),
                             *reinterpret_cast<unsigned*>(&h2), *reinterpret_cast<unsigned*>(&h3));
        *reinterpret_cast<uint4*>(yp + 8 * j) = u;
    }
}

// ============================ dinv + scale fused: dinv from fill count; T0 *= dinv ============================
__global__ void k_dinvscale(int n) {
    int idx = blockIdx.x * blockDim.x + threadIdx.x;
    if (idx >= n * 8) return;
    int node = idx >> 3;
    int c = (idx & 7) * 8;
    float dn = rsqrtf((float)(g_fill[node] + 1));   // true degree + self loop
    if ((idx & 7) == 0) g_dinv[node] = dn;
    __half* p = g_T0 + (size_t)node * 64 + c;
    uint4 u = *reinterpret_cast<uint4*>(p);
    __half2* h = reinterpret_cast<__half2*>(&u);
#pragma unroll
    for (int q = 0; q < 4; q++) {
        float2 f = __half22float2(h[q]);
        h[q] = __floats2half2_rn(f.x * dn, f.y * dn);
    }
    *reinterpret_cast<uint4*>(p) = u;
}

// a1 = P·1 from bucket gather of dinv (side stream, overlaps agg1)
__global__ void k_a1(int n) {
    int wid  = (blockIdx.x * blockDim.x + threadIdx.x) >> 5;
    int lane = threadIdx.x & 31;
    if (wid >= n) return;
    int cnt = min(g_fill[wid], BUCKET);
    const int* sp = g_src + (size_t)wid * BUCKET;
    float acc = 0.f;
    for (int e = lane; e < cnt; e += 32) acc += g_dinv[sp[e]];
    for (int d = 16; d; d >>= 1) acc += __shfl_down_sync(0xffffffffu, acc, d);
    if (lane == 0) {
        float dn = g_dinv[wid];
        float a1 = dn * (acc + dn);
        g_a1[wid] = a1;
        g_at[wid] = dn * a1;
    }
}

// a2 = P·a1 (side stream, overlaps agg2/agg3)
__global__ void k_a2(int n) {
    int wid  = (blockIdx.x * blockDim.x + threadIdx.x) >> 5;
    int lane = threadIdx.x & 31;
    if (wid >= n) return;
    int cnt = min(g_fill[wid], BUCKET);
    const int* sp = g_src + (size_t)wid * BUCKET;
    float acc = 0.f;
    for (int e = lane; e < cnt; e += 32) acc += g_at[sp[e]];
    for (int d = 16; d; d >>= 1) acc += __shfl_down_sync(0xffffffffu, acc, d);
    if (lane == 0) g_a2[wid] = g_dinv[wid] * (acc + g_at[wid]);
}

// ============================ weightless aggregation (R8-proven gather body, bucket addressing) ============================
// G[c] = sum_{src in bucket} X[src] + X[c];  MODE 0: fp16 out (dinv²), MODE 1: fp32 out (dinv)
template <int MODE>
__global__ void __launch_bounds__(256) k_aggp(const __half* __restrict__ X,
                                              void* __restrict__ Yv, int n) {
    int wid  = (blockIdx.x * blockDim.x + threadIdx.x) >> 5;
    int lane = threadIdx.x & 31;
    if (wid >= n) return;

    const int f0 = lane * 2;
    const int* sp = g_src + (size_t)wid * BUCKET;
    const int cnt = min(g_fill[wid], BUCKET);
    int e = 0;
    float a0 = 0.f, a1v = 0.f;

#define GATH(SRC) { __half2 h = *reinterpret_cast<const __half2*>(X + (size_t)(SRC) * 64 + f0); \
                    float2 f = __half22float2(h); a0 += f.x; a1v += f.y; }

    for (; e + 8 <= cnt; e += 8) {
        int s0 = sp[e+0], s1 = sp[e+1], s2 = sp[e+2], s3 = sp[e+3];
        int s4 = sp[e+4], s5 = sp[e+5], s6 = sp[e+6], s7 = sp[e+7];
        GATH(s0) GATH(s1) GATH(s2) GATH(s3) GATH(s4) GATH(s5) GATH(s6) GATH(s7)
    }
    for (; e < cnt; ++e) { int s = sp[e]; GATH(s) }
    GATH(wid)  // self loop
#undef GATH

    float dn = g_dinv[wid];
    if (MODE == 0) {
        float s = dn * dn;
        __half2 h = __floats2half2_rn(a0 * s, a1v * s);
        *reinterpret_cast<__half2*>((__half*)Yv + (size_t)wid * 64 + f0) = h;
    } else {
        *reinterpret_cast<float2*>((float*)Yv + (size_t)wid * 64 + f0) =
            make_float2(a0 * dn, a1v * dn);
    }
}

// ============================ final GEMM (also self-cleans g_fill for next replay) ============================
__global__ void __launch_bounds__(256) k_gemm_final(const float* __restrict__ A,
                                                    const float* __restrict__ Wg,
                                                    float* __restrict__ Y, int n) {
    __shared__ __align__(16) float sW[64 * 64];
    __shared__ float sc[64], se[64], sf[64];
    for (int i = threadIdx.x; i < 64 * 64; i += blockDim.x) sW[i] = Wg[i];
    if (threadIdx.x < 64) {
        sc[threadIdx.x] = g_c4[threadIdx.x];
        se[threadIdx.x] = g_e4[threadIdx.x];
        sf[threadIdx.x] = g_f4[threadIdx.x];
    }
    __syncthreads();
    int node = blockIdx.x * blockDim.x + threadIdx.x;
    if (node >= n) return;
    g_fill[node] = 0;   // self-clean for next replay (all bucket readers are done)

    unsigned long long acc[32];
#pragma unroll
    for (int j = 0; j < 32; j++) acc[j] = 0ull;

    const float* arow = A + (size_t)node * 64;
#pragma unroll 2
    for (int k = 0; k < 64; k += 4) {
        float4 av = *reinterpret_cast<const float4*>(arow + k);
        unsigned long long p0 = pack2(av.x), p1 = pack2(av.y);
        unsigned long long p2 = pack2(av.z), p3 = pack2(av.w);
        const ulonglong2* w0 = reinterpret_cast<const ulonglong2*>(sW + (k + 0) * 64);
        const ulonglong2* w1 = reinterpret_cast<const ulonglong2*>(sW + (k + 1) * 64);
        const ulonglong2* w2 = reinterpret_cast<const ulonglong2*>(sW + (k + 2) * 64);
        const ulonglong2* w3 = reinterpret_cast<const ulonglong2*>(sW + (k + 3) * 64);
#pragma unroll
        for (int j = 0; j < 16; j++) {
            ulonglong2 q;
            q = w0[j]; acc[2*j] = ffma2(p0, q.x, acc[2*j]); acc[2*j+1] = ffma2(p0, q.y, acc[2*j+1]);
            q = w1[j]; acc[2*j] = ffma2(p1, q.x, acc[2*j]); acc[2*j+1] = ffma2(p1, q.y, acc[2*j+1]);
            q = w2[j]; acc[2*j] = ffma2(p2, q.x, acc[2*j]); acc[2*j+1] = ffma2(p2, q.y, acc[2*j+1]);
            q = w3[j]; acc[2*j] = ffma2(p3, q.x, acc[2*j]); acc[2*j+1] = ffma2(p3, q.y, acc[2*j+1]);
        }
    }

    float av1 = g_a1[node], av2 = g_a2[node];
    float* yrow = Y + (size_t)node * 64;
#pragma unroll
    for (int j = 0; j < 16; j++) {
        float2 lo = unpack2(acc[2*j]);
        float2 hi = unpack2(acc[2*j+1]);
        int c0 = 4 * j;
        float4 o;
        o.x = lo.x + av2 * sc[c0+0] + av1 * se[c0+0] + sf[c0+0];
        o.y = lo.y + av2 * sc[c0+1] + av1 * se[c0+1] + sf[c0+1];
        o.z = hi.x + av2 * sc[c0+2] + av1 * se[c0+2] + sf[c0+2];
        o.w = hi.y + av2 * sc[c0+3] + av1 * se[c0+3] + sf[c0+3];
        *reinterpret_cast<float4*>(yrow + c0) = o;
    }
}

// ============================ launch ============================

extern "C" void kernel_launch(void* const* d_in, const int* in_sizes, int n_in,
                              void* d_out, int out_size) {
    const float* latent = (const float*)d_in[0];
    const float* cond   = (const float*)d_in[1];
    const int*   edge   = (const int*)  d_in[2];
    const float* W1 = (const float*)d_in[3];
    const float* b1 = (const float*)d_in[4];
    const float* W2 = (const float*)d_in[5];
    const float* b2 = (const float*)d_in[6];
    const float* W3 = (const float*)d_in[7];
    const float* b3 = (const float*)d_in[8];
    const float* W4 = (const float*)d_in[9];
    const float* b4 = (const float*)d_in[10];

    const int n = in_sizes[0] / 64;      // 100000
    const int E = in_sizes[2] / 2;       // 1600000
    const int* row = edge;
    const int* col = edge + E;

    static __half *pT0 = nullptr, *pT1 = nullptr, *pT2 = nullptr;
    static float *pY3 = nullptr;
    static cudaStream_t sB = nullptr;
    static cudaEvent_t ev0 = nullptr, evG0 = nullptr, evDS = nullptr, evA2 = nullptr;
    if (!pT0) {
        cudaGetSymbolAddress((void**)&pT0,  g_T0);
        cudaGetSymbolAddress((void**)&pT1,  g_T1);
        cudaGetSymbolAddress((void**)&pT2,  g_T2);
        cudaGetSymbolAddress((void**)&pY3,  g_Y3);
        cudaStreamCreateWithFlags(&sB, cudaStreamNonBlocking);
        cudaEventCreateWithFlags(&ev0,  cudaEventDisableTiming);
        cudaEventCreateWithFlags(&evG0, cudaEventDisableTiming);
        cudaEventCreateWithFlags(&evDS, cudaEventDisableTiming);
        cudaEventCreateWithFlags(&evA2, cudaEventDisableTiming);
    }

    const int TB  = 256;
    const int gN  = (n + TB - 1) / TB;
    const int gE  = (E + TB - 1) / TB;
    const int gW  = (n + 7) / 8;            // warp per node, 8 warps/block
    const int gS  = (n * 8 + TB - 1) / TB;  // dinvscale kernel

    // ---- fork: side stream B computes the weight path ----
    cudaEventRecord(ev0, 0);
    cudaStreamWaitEvent(sB, ev0, 0);
    k_wprep2<<<25, 256, 0, sB>>>(W1, W2, W3, W4, b1, b2, b3, b4);
    k_gemm0v<<<gN, TB, 0, sB>>>(latent, cond, n);   // V = [L|C]@U (unscaled)
    cudaEventRecord(evG0, sB);

    // ---- main stream: bucketed fill (no hist, no scan) ----
    k_fill<<<gE, TB>>>(row, col, E);

    // ---- main: dinv from fill counts + scale T0 (needs gemm0v) ----
    cudaStreamWaitEvent(0, evG0, 0);
    k_dinvscale<<<gS, TB>>>(n);
    cudaEventRecord(evDS, 0);

    // ---- side stream: a1 then a2 (need buckets + dinv), overlap aggs ----
    cudaStreamWaitEvent(sB, evDS, 0);
    k_a1<<<gW, TB, 0, sB>>>(n);
    k_a2<<<gW, TB, 0, sB>>>(n);
    cudaEventRecord(evA2, sB);

    // ---- main: three aggregation passes ----
    k_aggp<0><<<gW, TB>>>(pT0, pT1, n);
    k_aggp<0><<<gW, TB>>>(pT1, pT2, n);
    k_aggp<1><<<gW, TB>>>(pT2, pY3, n);

    // ---- out = Y3@W4 + a2·c4 + a1·e4 + f4 (+ self-clean) ----
    cudaStreamWaitEvent(0, evA2, 0);
    k_gemm_final<<<gN, TB>>>(pY3, W4, (float*)d_out, n);
}

// round 13
// speedup vs baseline: 1.1521x; 1.1324x over previous
#include <cuda_runtime.h>
#include <cuda_fp16.h>

// ===== static scratch (allocation-free rule: __device__ globals) =====
#define N_MAX 100352
#define E_MAX 1700032

__device__ int   g_cnt[N_MAX];       // zero at load; self-cleaned by k_a2 each run
__device__ int   g_fill[N_MAX];
__device__ int   g_off[N_MAX + 1];
__device__ int   g_bsum[1024];
__device__ float g_dinv[N_MAX];
__device__ float g_a1f[N_MAX];       // atomic accum of sum dinv[src]; self-cleaned by k_a2
__device__ int   g_src[E_MAX];       // CSR src indices (weightless)

__device__ float g_a1[N_MAX];        // P·1
__device__ float g_at[N_MAX];        // dinv * a1
__device__ float g_a2[N_MAX];        // P²·1
__device__ float g_U [96 * 64];      // [W1@W3_top ; W2@W3_bot]
__device__ float g_U2[96 * 64];      // U @ W4
__device__ float g_c4[64];           // ([b1|b2]@W3)@W4
__device__ float g_e4[64];           // b3@W4
__device__ float g_f4[64];           // b4

__device__ __align__(16) __half g_T0[(size_t)N_MAX * 64];  // Z, then Dinv·Z (in place)
__device__ __align__(16) __half g_T1[(size_t)N_MAX * 64];
__device__ __align__(16) __half g_T2[(size_t)N_MAX * 64];

// ===== packed fp32x2 helpers (sm_103a) =====
__device__ __forceinline__ unsigned long long ffma2(unsigned long long a,
                                                    unsigned long long b,
                                                    unsigned long long c) {
    unsigned long long d;
    asm("fma.rn.f32x2 %0, %1, %2, %3;" : "=l"(d) : "l"(a), "l"(b), "l"(c));
    return d;
}
__device__ __forceinline__ unsigned long long pack2(float x) {
    unsigned long long d;
    asm("mov.b64 %0, {%1, %1};" : "=l"(d) : "r"(__float_as_uint(x)));
    return d;
}
__device__ __forceinline__ float2 unpack2(unsigned long long v) {
    unsigned int lo, hi;
    asm("mov.b64 {%0, %1}, %2;" : "=r"(lo), "=r"(hi) : "l"(v));
    return make_float2(__uint_as_float(lo), __uint_as_float(hi));
}

// ============================ graph construction ============================

__global__ void k_hist(const int* __restrict__ col, int E) {
    int e = blockIdx.x * blockDim.x + threadIdx.x;
    if (e < E) atomicAdd(&g_cnt[col[e]], 1);
}

__global__ void __launch_bounds__(1024) k_scan_local(int n) {
    __shared__ int s[1024];
    int tid = threadIdx.x;
    int i = blockIdx.x * 1024 + tid;
    int v = (i < n) ? g_cnt[i] : 0;
    s[tid] = v;
    __syncthreads();
    for (int d = 1; d < 1024; d <<= 1) {
        int t = (tid >= d) ? s[tid - d] : 0;
        __syncthreads();
        s[tid] += t;
        __syncthreads();
    }
    if (i < n) g_off[i] = s[tid] - v;
    if (tid == 1023) g_bsum[blockIdx.x] = s[1023];
}

// merged: every block re-scans the <=128 per-block sums in smem, then finalizes.
__global__ void __launch_bounds__(256) k_scan_add(int n, int E, int nb) {
    __shared__ int sb[128];
    int tid = threadIdx.x;
    if (tid < 128) sb[tid] = (tid < nb) ? g_bsum[tid] : 0;
    __syncthreads();
    for (int d = 1; d < 128; d <<= 1) {
        int t = (tid >= d && tid < 128) ? sb[tid - d] : 0;
        __syncthreads();
        if (tid < 128) sb[tid] += t;   // inclusive
        __syncthreads();
    }
    int i = blockIdx.x * blockDim.x + tid;
    if (i < n) {
        int b = i >> 10;
        int pre = b ? sb[b - 1] : 0;
        int o = g_off[i] + pre;
        g_off[i]  = o;
        g_fill[i] = o;
        g_dinv[i] = rsqrtf((float)(g_cnt[i] + 1));
    }
    if (i == n) g_off[n] = E;
}

// fill CSR src; accumulate a1f[c] += dinv[r]
__global__ void k_fill(const int* __restrict__ row, const int* __restrict__ col, int E) {
    int e = blockIdx.x * blockDim.x + threadIdx.x;
    if (e < E) {
        int r = row[e], c = col[e];
        int pos = atomicAdd(&g_fill[c], 1);
        g_src[pos] = r;
        atomicAdd(&g_a1f[c], g_dinv[r]);
    }
}

// ============================ weight precompute (side stream) ============================
// stage A: U = [W1;W2] @ W3   (24 tile blocks)
__global__ void __launch_bounds__(256) k_wprep_a(
        const float* __restrict__ W1, const float* __restrict__ W2,
        const float* __restrict__ W3) {
    __shared__ float sB[64 * 64];
    __shared__ float sA[4 * 64];
    int tid = threadIdx.x;
    int k0 = blockIdx.x * 4;
    int half = (k0 >= 64);
    const float* Wsrc = W3 + (size_t)half * 64 * 64;
    for (int i = tid; i < 64 * 64; i += 256) sB[i] = Wsrc[i];
    const float* Arow = half ? (W2 + (size_t)(k0 - 64) * 64) : (W1 + (size_t)k0 * 64);
    sA[tid] = Arow[tid];
    __syncthreads();
    int k = tid >> 6, j = tid & 63;
    float s = 0.f;
#pragma unroll
    for (int m = 0; m < 64; m++) s += sA[k * 64 + m] * sB[m * 64 + j];
    g_U[(k0 + k) * 64 + j] = s;
}

// stage B: U2 = U @ W4 (24 tile blocks) + bias vectors (block 24)
__global__ void __launch_bounds__(256) k_wprep_b(
        const float* __restrict__ W3, const float* __restrict__ W4,
        const float* __restrict__ b1, const float* __restrict__ b2,
        const float* __restrict__ b3, const float* __restrict__ b4) {
    int tid = threadIdx.x;
    int b = blockIdx.x;
    if (b < 24) {
        __shared__ float sB[64 * 64];
        __shared__ float sA[4 * 64];
        int k0 = b * 4;
        for (int i = tid; i < 64 * 64; i += 256) sB[i] = W4[i];
        sA[tid] = g_U[(size_t)k0 * 64 + tid];
        __syncthreads();
        int k = tid >> 6, j = tid & 63;
        float s = 0.f;
#pragma unroll
        for (int m = 0; m < 64; m++) s += sA[k * 64 + m] * sB[m * 64 + j];
        g_U2[(k0 + k) * 64 + j] = s;
    } else {
        __shared__ float c3[64];
        int j = tid & 63;
        if (tid < 64) {
            float s = 0.f;
            for (int m = 0; m < 128; m++)
                s += ((m < 64) ? b1[m] : b2[m - 64]) * W3[m * 64 + j];
            c3[j] = s;
        }
        __syncthreads();
        if (tid < 64) {
            float s = 0.f, t = 0.f;
            for (int m = 0; m < 64; m++) {
                s += c3[m] * W4[m * 64 + j];
                t += b3[m] * W4[m * 64 + j];
            }
            g_c4[j] = s; g_e4[j] = t; g_f4[j] = b4[j];
        }
    }
}

// ============================ gemm0v: Z = [L|C]@U2 (fp16, unscaled; side stream) ============================
__global__ void __launch_bounds__(256) k_gemm0v(const float* __restrict__ latent,
                                                const float* __restrict__ cond, int n) {
    __shared__ __align__(16) float sW[96 * 64];
    for (int i = threadIdx.x; i < 96 * 64; i += blockDim.x) sW[i] = g_U2[i];
    __syncthreads();
    int node = blockIdx.x * blockDim.x + threadIdx.x;
    if (node >= n) return;

    unsigned long long acc[32];
#pragma unroll
    for (int j = 0; j < 32; j++) acc[j] = 0ull;

    const float* pL = latent + (size_t)node * 64;
    const float* pC = cond   + (size_t)node * 32;
#pragma unroll 2
    for (int k = 0; k < 96; k += 4) {
        float4 av = (k < 64) ? *reinterpret_cast<const float4*>(pL + k)
                             : *reinterpret_cast<const float4*>(pC + (k - 64));
        unsigned long long p0 = pack2(av.x), p1 = pack2(av.y);
        unsigned long long p2 = pack2(av.z), p3 = pack2(av.w);
        const ulonglong2* w0 = reinterpret_cast<const ulonglong2*>(sW + (k + 0) * 64);
        const ulonglong2* w1 = reinterpret_cast<const ulonglong2*>(sW + (k + 1) * 64);
        const ulonglong2* w2 = reinterpret_cast<const ulonglong2*>(sW + (k + 2) * 64);
        const ulonglong2* w3 = reinterpret_cast<const ulonglong2*>(sW + (k + 3) * 64);
#pragma unroll
        for (int j = 0; j < 16; j++) {
            ulonglong2 q;
            q = w0[j]; acc[2*j] = ffma2(p0, q.x, acc[2*j]); acc[2*j+1] = ffma2(p0, q.y, acc[2*j+1]);
            q = w1[j]; acc[2*j] = ffma2(p1, q.x, acc[2*j]); acc[2*j+1] = ffma2(p1, q.y, acc[2*j+1]);
            q = w2[j]; acc[2*j] = ffma2(p2, q.x, acc[2*j]); acc[2*j+1] = ffma2(p2, q.y, acc[2*j+1]);
            q = w3[j]; acc[2*j] = ffma2(p3, q.x, acc[2*j]); acc[2*j+1] = ffma2(p3, q.y, acc[2*j+1]);
        }
    }

    __half* yp = g_T0 + (size_t)node * 64;
#pragma unroll
    for (int j = 0; j < 8; j++) {
        float2 f0 = unpack2(acc[4*j+0]);
        float2 f1 = unpack2(acc[4*j+1]);
        float2 f2 = unpack2(acc[4*j+2]);
        float2 f3 = unpack2(acc[4*j+3]);
        __half2 h0 = __floats2half2_rn(f0.x, f0.y);
        __half2 h1 = __floats2half2_rn(f1.x, f1.y);
        __half2 h2 = __floats2half2_rn(f2.x, f2.y);
        __half2 h3 = __floats2half2_rn(f3.x, f3.y);
        uint4 u = make_uint4(*reinterpret_cast<unsigned*>(&h0), *reinterpret_cast<unsigned*>(&h1),
                             *reinterpret_cast<unsigned*>(&h2), *reinterpret_cast<unsigned*>(&h3));
        *reinterpret_cast<uint4*>(yp + 8 * j) = u;
    }
}

// ============================ scale: T0 *= dinv (in place; side stream, overlaps fill) ============================
__global__ void k_scale(int n) {
    int idx = blockIdx.x * blockDim.x + threadIdx.x;
    if (idx >= n * 8) return;
    int node = idx >> 3;
    int c = (idx & 7) * 8;
    float dn = g_dinv[node];
    __half* p = g_T0 + (size_t)node * 64 + c;
    uint4 u = *reinterpret_cast<uint4*>(p);
    __half2* h = reinterpret_cast<__half2*>(&u);
#pragma unroll
    for (int q = 0; q < 4; q++) {
        float2 f = __half22float2(h[q]);
        h[q] = __floats2half2_rn(f.x * dn, f.y * dn);
    }
    *reinterpret_cast<uint4*>(p) = u;
}

// a2 = P·a1 (side stream, overlaps agg2); also self-cleans cnt & a1f for next run
__global__ void k_a2(int n) {
    int wid  = (blockIdx.x * blockDim.x + threadIdx.x) >> 5;
    int lane = threadIdx.x & 31;
    if (wid >= n) return;
    int beg = g_off[wid], end = g_off[wid + 1];
    float acc = 0.f;
    for (int e = beg + lane; e < end; e += 32) acc += g_at[g_src[e]];
    for (int d = 16; d; d >>= 1) acc += __shfl_down_sync(0xffffffffu, acc, d);
    if (lane == 0) g_a2[wid] = g_dinv[wid] * (acc + g_at[wid]);
    if (lane == 1) g_cnt[wid] = 0;     // self-clean for next replay
    if (lane == 2) g_a1f[wid] = 0.f;
}

// ============================ weightless aggregation ============================
// G[c] = sum_{e->c} X[src_e] + X[c]
// MODE 0: fp16 out (dinv²);  MODE 1: FINAL — fp32 out = dinv·G + a2·c4 + a1·e4 + f4
// FIRST: lane0 finalizes a1/at from a1f (pass 1 only).
template <int MODE, bool FIRST>
__global__ void __launch_bounds__(256) k_aggp(const __half* __restrict__ X,
                                              void* __restrict__ Yv, int n) {
    int wid  = (blockIdx.x * blockDim.x + threadIdx.x) >> 5;
    int lane = threadIdx.x & 31;
    if (wid >= n) return;

    const int f0 = lane * 2;
    int e = g_off[wid];
    const int end = g_off[wid + 1];
    float a0 = 0.f, a1v = 0.f;

#define GATH(SRC) { __half2 h = *reinterpret_cast<const __half2*>(X + (size_t)(SRC) * 64 + f0); \
                    float2 f = __half22float2(h); a0 += f.x; a1v += f.y; }

    for (; e + 8 <= end; e += 8) {
        int s0 = g_src[e+0], s1 = g_src[e+1], s2 = g_src[e+2], s3 = g_src[e+3];
        int s4 = g_src[e+4], s5 = g_src[e+5], s6 = g_src[e+6], s7 = g_src[e+7];
        GATH(s0) GATH(s1) GATH(s2) GATH(s3) GATH(s4) GATH(s5) GATH(s6) GATH(s7)
    }
    for (; e < end; ++e) { int s = g_src[e]; GATH(s) }
    GATH(wid)  // self loop
#undef GATH

    float dn = g_dinv[wid];
    if (FIRST && lane == 0) {
        float a1 = dn * (g_a1f[wid] + dn);
        g_a1[wid] = a1;
        g_at[wid] = dn * a1;
    }
    if (MODE == 0) {
        float s = dn * dn;
        __half2 h = __floats2half2_rn(a0 * s, a1v * s);
        *reinterpret_cast<__half2*>((__half*)Yv + (size_t)wid * 64 + f0) = h;
    } else {
        float av1 = g_a1[wid], av2 = g_a2[wid];
        float2 c4v = *reinterpret_cast<const float2*>(g_c4 + f0);
        float2 e4v = *reinterpret_cast<const float2*>(g_e4 + f0);
        float2 f4v = *reinterpret_cast<const float2*>(g_f4 + f0);
        float2 o;
        o.x = a0  * dn + av2 * c4v.x + av1 * e4v.x + f4v.x;
        o.y = a1v * dn + av2 * c4v.y + av1 * e4v.y + f4v.y;
        *reinterpret_cast<float2*>((float*)Yv + (size_t)wid * 64 + f0) = o;
    }
}

// ============================ launch ============================

extern "C" void kernel_launch(void* const* d_in, const int* in_sizes, int n_in,
                              void* d_out, int out_size) {
    const float* latent = (const float*)d_in[0];
    const float* cond   = (const float*)d_in[1];
    const int*   edge   = (const int*)  d_in[2];
    const float* W1 = (const float*)d_in[3];
    const float* b1 = (const float*)d_in[4];
    const float* W2 = (const float*)d_in[5];
    const float* b2 = (const float*)d_in[6];
    const float* W3 = (const float*)d_in[7];
    const float* b3 = (const float*)d_in[8];
    const float* W4 = (const float*)d_in[9];
    const float* b4 = (const float*)d_in[10];

    const int n = in_sizes[0] / 64;      // 100000
    const int E = in_sizes[2] / 2;       // 1600000
    const int* row = edge;
    const int* col = edge + E;

    static __half *pT0 = nullptr, *pT1 = nullptr, *pT2 = nullptr;
    static cudaStream_t sB = nullptr;
    static cudaEvent_t ev0 = nullptr, evAdd = nullptr, evScale = nullptr,
                       evAgg1 = nullptr, evA2 = nullptr;
    if (!pT0) {
        cudaGetSymbolAddress((void**)&pT0, g_T0);
        cudaGetSymbolAddress((void**)&pT1, g_T1);
        cudaGetSymbolAddress((void**)&pT2, g_T2);
        cudaStreamCreateWithFlags(&sB, cudaStreamNonBlocking);
        cudaEventCreateWithFlags(&ev0,     cudaEventDisableTiming);
        cudaEventCreateWithFlags(&evAdd,   cudaEventDisableTiming);
        cudaEventCreateWithFlags(&evScale, cudaEventDisableTiming);
        cudaEventCreateWithFlags(&evAgg1,  cudaEventDisableTiming);
        cudaEventCreateWithFlags(&evA2,    cudaEventDisableTiming);
    }

    const int TB  = 256;
    const int gN  = (n + TB - 1) / TB;
    const int gE  = (E + TB - 1) / TB;
    const int nbS = (n + 1023) / 1024;      // <= 98 <= 128
    const int gN1 = (n + 1 + TB - 1) / TB;
    const int gW  = (n + 7) / 8;            // warp per node, 8 warps/block
    const int gS  = (n * 8 + TB - 1) / TB;  // scale kernel

    // ---- fork: side stream B computes the weight path ----
    cudaEventRecord(ev0, 0);
    cudaStreamWaitEvent(sB, ev0, 0);
    k_wprep_a<<<24, 256, 0, sB>>>(W1, W2, W3);
    k_wprep_b<<<25, 256, 0, sB>>>(W3, W4, b1, b2, b3, b4);
    k_gemm0v<<<gN, TB, 0, sB>>>(latent, cond, n);   // Z = [L|C]@U2 (unscaled)

    // ---- main stream: edge/build chain ----
    k_hist<<<gE, TB>>>(col, E);
    k_scan_local<<<nbS, 1024>>>(n);
    k_scan_add<<<gN1, TB>>>(n, E, nbS);
    cudaEventRecord(evAdd, 0);
    k_fill<<<gE, TB>>>(row, col, E);

    // ---- side stream: scale T0 by dinv (needs scan_add + gemm0v), overlaps fill ----
    cudaStreamWaitEvent(sB, evAdd, 0);
    k_scale<<<gS, TB, 0, sB>>>(n);
    cudaEventRecord(evScale, sB);

    // ---- main stream: agg1 (finalizes a1/at), agg2 ----
    cudaStreamWaitEvent(0, evScale, 0);
    k_aggp<0, true ><<<gW, TB>>>(pT0, pT1, n);
    cudaEventRecord(evAgg1, 0);
    k_aggp<0, false><<<gW, TB>>>(pT1, pT2, n);

    // ---- side stream: a2 gather (needs agg1's a1/at), overlaps agg2 ----
    cudaStreamWaitEvent(sB, evAgg1, 0);
    k_a2<<<gW, TB, 0, sB>>>(n);
    cudaEventRecord(evA2, sB);

    // ---- final agg writes out = P³Z·(folded W4) + a2·c4 + a1·e4 + f4 ----
    cudaStreamWaitEvent(0, evA2, 0);
    k_aggp<1, false><<<gW, TB>>>(pT2, (float*)d_out, n);
}

// round 14
// speedup vs baseline: 1.1799x; 1.0242x over previous
#include <cuda_runtime.h>
#include <cuda_fp16.h>

// ===== static scratch (allocation-free rule: __device__ globals) =====
#define N_MAX 100352
#define E_MAX 1700032

__device__ int                g_cnt[N_MAX];    // zero at load; self-cleaned by k_a2 each run
__device__ unsigned long long g_pack[N_MAX];   // (cursor<<32)|fixedpoint dinv-sum; seeded by scan_add
__device__ int   g_off[N_MAX + 1];
__device__ int   g_bsum[1024];
__device__ float g_dinv[N_MAX];
__device__ int   g_src[E_MAX];       // CSR src indices (weightless)

__device__ float g_a1[N_MAX];        // P·1
__device__ float g_at[N_MAX];        // dinv * a1
__device__ float g_a2[N_MAX];        // P²·1
__device__ float g_U [96 * 64];      // [W1@W3_top ; W2@W3_bot]
__device__ float g_U2[96 * 64];      // U @ W4
__device__ float g_c4[64];           // ([b1|b2]@W3)@W4
__device__ float g_e4[64];           // b3@W4
__device__ float g_f4[64];           // b4

__device__ __align__(16) __half g_T0[(size_t)N_MAX * 64];  // Z, then Dinv·Z (in place)
__device__ __align__(16) __half g_T1[(size_t)N_MAX * 64];
__device__ __align__(16) __half g_T2[(size_t)N_MAX * 64];

#define FIXP 16777216.0f   // 2^24

// ===== packed fp32x2 helpers (sm_103a) =====
__device__ __forceinline__ unsigned long long ffma2(unsigned long long a,
                                                    unsigned long long b,
                                                    unsigned long long c) {
    unsigned long long d;
    asm("fma.rn.f32x2 %0, %1, %2, %3;" : "=l"(d) : "l"(a), "l"(b), "l"(c));
    return d;
}
__device__ __forceinline__ unsigned long long pack2(float x) {
    unsigned long long d;
    asm("mov.b64 %0, {%1, %1};" : "=l"(d) : "r"(__float_as_uint(x)));
    return d;
}
__device__ __forceinline__ float2 unpack2(unsigned long long v) {
    unsigned int lo, hi;
    asm("mov.b64 {%0, %1}, %2;" : "=r"(lo), "=r"(hi) : "l"(v));
    return make_float2(__uint_as_float(lo), __uint_as_float(hi));
}

// ============================ graph construction ============================

// 4 edges per thread for MLP on the atomics
__global__ void k_hist(const int* __restrict__ col, int E) {
    int e = (blockIdx.x * blockDim.x + threadIdx.x) * 4;
    if (e + 4 <= E) {
        int4 c = *reinterpret_cast<const int4*>(col + e);
        atomicAdd(&g_cnt[c.x], 1);
        atomicAdd(&g_cnt[c.y], 1);
        atomicAdd(&g_cnt[c.z], 1);
        atomicAdd(&g_cnt[c.w], 1);
    } else {
        for (; e < E; e++) atomicAdd(&g_cnt[col[e]], 1);
    }
}

__global__ void __launch_bounds__(1024) k_scan_local(int n) {
    __shared__ int s[1024];
    int tid = threadIdx.x;
    int i = blockIdx.x * 1024 + tid;
    int v = (i < n) ? g_cnt[i] : 0;
    s[tid] = v;
    __syncthreads();
    for (int d = 1; d < 1024; d <<= 1) {
        int t = (tid >= d) ? s[tid - d] : 0;
        __syncthreads();
        s[tid] += t;
        __syncthreads();
    }
    if (i < n) g_off[i] = s[tid] - v;
    if (tid == 1023) g_bsum[blockIdx.x] = s[1023];
}

// merged: every block re-scans the <=128 per-block sums in smem, then finalizes.
// Seeds g_pack with (offset<<32) so fill's packed atomic returns global positions.
__global__ void __launch_bounds__(256) k_scan_add(int n, int E, int nb) {
    __shared__ int sb[128];
    int tid = threadIdx.x;
    if (tid < 128) sb[tid] = (tid < nb) ? g_bsum[tid] : 0;
    __syncthreads();
    for (int d = 1; d < 128; d <<= 1) {
        int t = (tid >= d && tid < 128) ? sb[tid - d] : 0;
        __syncthreads();
        if (tid < 128) sb[tid] += t;   // inclusive
        __syncthreads();
    }
    int i = blockIdx.x * blockDim.x + tid;
    if (i < n) {
        int b = i >> 10;
        int pre = b ? sb[b - 1] : 0;
        int o = g_off[i] + pre;
        g_off[i]  = o;
        g_pack[i] = (unsigned long long)(unsigned)o << 32;
        g_dinv[i] = rsqrtf((float)(g_cnt[i] + 1));
    }
    if (i == n) g_off[n] = E;
}

// fill CSR src with ONE packed 64-bit atomic per edge (cursor + fixedpoint dinv-sum)
__global__ void k_fill(const int* __restrict__ row, const int* __restrict__ col, int E) {
    int e = blockIdx.x * blockDim.x + threadIdx.x;
    if (e < E) {
        int r = row[e], c = col[e];
        unsigned q = (unsigned)__float2uint_rn(g_dinv[r] * FIXP);
        unsigned long long ret =
            atomicAdd(&g_pack[c], ((unsigned long long)1 << 32) | (unsigned long long)q);
        int pos = (int)(ret >> 32);
        g_src[pos] = r;
    }
}

// ============================ weight precompute (side stream) ============================
// stage A: U = [W1;W2] @ W3   (24 tile blocks)
__global__ void __launch_bounds__(256) k_wprep_a(
        const float* __restrict__ W1, const float* __restrict__ W2,
        const float* __restrict__ W3) {
    __shared__ float sB[64 * 64];
    __shared__ float sA[4 * 64];
    int tid = threadIdx.x;
    int k0 = blockIdx.x * 4;
    int half = (k0 >= 64);
    const float* Wsrc = W3 + (size_t)half * 64 * 64;
    for (int i = tid; i < 64 * 64; i += 256) sB[i] = Wsrc[i];
    const float* Arow = half ? (W2 + (size_t)(k0 - 64) * 64) : (W1 + (size_t)k0 * 64);
    sA[tid] = Arow[tid];
    __syncthreads();
    int k = tid >> 6, j = tid & 63;
    float s = 0.f;
#pragma unroll
    for (int m = 0; m < 64; m++) s += sA[k * 64 + m] * sB[m * 64 + j];
    g_U[(k0 + k) * 64 + j] = s;
}

// stage B: U2 = U @ W4 (24 tile blocks) + bias vectors (block 24)
__global__ void __launch_bounds__(256) k_wprep_b(
        const float* __restrict__ W3, const float* __restrict__ W4,
        const float* __restrict__ b1, const float* __restrict__ b2,
        const float* __restrict__ b3, const float* __restrict__ b4) {
    int tid = threadIdx.x;
    int b = blockIdx.x;
    if (b < 24) {
        __shared__ float sB[64 * 64];
        __shared__ float sA[4 * 64];
        int k0 = b * 4;
        for (int i = tid; i < 64 * 64; i += 256) sB[i] = W4[i];
        sA[tid] = g_U[(size_t)k0 * 64 + tid];
        __syncthreads();
        int k = tid >> 6, j = tid & 63;
        float s = 0.f;
#pragma unroll
        for (int m = 0; m < 64; m++) s += sA[k * 64 + m] * sB[m * 64 + j];
        g_U2[(k0 + k) * 64 + j] = s;
    } else {
        __shared__ float c3[64];
        int j = tid & 63;
        if (tid < 64) {
            float s = 0.f;
            for (int m = 0; m < 128; m++)
                s += ((m < 64) ? b1[m] : b2[m - 64]) * W3[m * 64 + j];
            c3[j] = s;
        }
        __syncthreads();
        if (tid < 64) {
            float s = 0.f, t = 0.f;
            for (int m = 0; m < 64; m++) {
                s += c3[m] * W4[m * 64 + j];
                t += b3[m] * W4[m * 64 + j];
            }
            g_c4[j] = s; g_e4[j] = t; g_f4[j] = b4[j];
        }
    }
}

// ============================ gemm0v: Z = [L|C]@U2 (fp16, unscaled; side stream) ============================
__global__ void __launch_bounds__(256) k_gemm0v(const float* __restrict__ latent,
                                                const float* __restrict__ cond, int n) {
    __shared__ __align__(16) float sW[96 * 64];
    for (int i = threadIdx.x; i < 96 * 64; i += blockDim.x) sW[i] = g_U2[i];
    __syncthreads();
    int node = blockIdx.x * blockDim.x + threadIdx.x;
    if (node >= n) return;

    unsigned long long acc[32];
#pragma unroll
    for (int j = 0; j < 32; j++) acc[j] = 0ull;

    const float* pL = latent + (size_t)node * 64;
    const float* pC = cond   + (size_t)node * 32;
#pragma unroll 2
    for (int k = 0; k < 96; k += 4) {
        float4 av = (k < 64) ? *reinterpret_cast<const float4*>(pL + k)
                             : *reinterpret_cast<const float4*>(pC + (k - 64));
        unsigned long long p0 = pack2(av.x), p1 = pack2(av.y);
        unsigned long long p2 = pack2(av.z), p3 = pack2(av.w);
        const ulonglong2* w0 = reinterpret_cast<const ulonglong2*>(sW + (k + 0) * 64);
        const ulonglong2* w1 = reinterpret_cast<const ulonglong2*>(sW + (k + 1) * 64);
        const ulonglong2* w2 = reinterpret_cast<const ulonglong2*>(sW + (k + 2) * 64);
        const ulonglong2* w3 = reinterpret_cast<const ulonglong2*>(sW + (k + 3) * 64);
#pragma unroll
        for (int j = 0; j < 16; j++) {
            ulonglong2 q;
            q = w0[j]; acc[2*j] = ffma2(p0, q.x, acc[2*j]); acc[2*j+1] = ffma2(p0, q.y, acc[2*j+1]);
            q = w1[j]; acc[2*j] = ffma2(p1, q.x, acc[2*j]); acc[2*j+1] = ffma2(p1, q.y, acc[2*j+1]);
            q = w2[j]; acc[2*j] = ffma2(p2, q.x, acc[2*j]); acc[2*j+1] = ffma2(p2, q.y, acc[2*j+1]);
            q = w3[j]; acc[2*j] = ffma2(p3, q.x, acc[2*j]); acc[2*j+1] = ffma2(p3, q.y, acc[2*j+1]);
        }
    }

    __half* yp = g_T0 + (size_t)node * 64;
#pragma unroll
    for (int j = 0; j < 8; j++) {
        float2 f0 = unpack2(acc[4*j+0]);
        float2 f1 = unpack2(acc[4*j+1]);
        float2 f2 = unpack2(acc[4*j+2]);
        float2 f3 = unpack2(acc[4*j+3]);
        __half2 h0 = __floats2half2_rn(f0.x, f0.y);
        __half2 h1 = __floats2half2_rn(f1.x, f1.y);
        __half2 h2 = __floats2half2_rn(f2.x, f2.y);
        __half2 h3 = __floats2half2_rn(f3.x, f3.y);
        uint4 u = make_uint4(*reinterpret_cast<unsigned*>(&h0), *reinterpret_cast<unsigned*>(&h1),
                             *reinterpret_cast<unsigned*>(&h2), *reinterpret_cast<unsigned*>(&h3));
        *reinterpret_cast<uint4*>(yp + 8 * j) = u;
    }
}

// ============================ scale: T0 *= dinv (in place; side stream, overlaps fill) ============================
__global__ void k_scale(int n) {
    int idx = blockIdx.x * blockDim.x + threadIdx.x;
    if (idx >= n * 8) return;
    int node = idx >> 3;
    int c = (idx & 7) * 8;
    float dn = g_dinv[node];
    __half* p = g_T0 + (size_t)node * 64 + c;
    uint4 u = *reinterpret_cast<uint4*>(p);
    __half2* h = reinterpret_cast<__half2*>(&u);
#pragma unroll
    for (int q = 0; q < 4; q++) {
        float2 f = __half22float2(h[q]);
        h[q] = __floats2half2_rn(f.x * dn, f.y * dn);
    }
    *reinterpret_cast<uint4*>(p) = u;
}

// a2 = P·a1 (side stream, overlaps agg2); also self-cleans g_cnt for next run
__global__ void k_a2(int n) {
    int wid  = (blockIdx.x * blockDim.x + threadIdx.x) >> 5;
    int lane = threadIdx.x & 31;
    if (wid >= n) return;
    int beg = g_off[wid], end = g_off[wid + 1];
    float acc = 0.f;
    for (int e = beg + lane; e < end; e += 32) acc += g_at[g_src[e]];
    for (int d = 16; d; d >>= 1) acc += __shfl_down_sync(0xffffffffu, acc, d);
    if (lane == 0) g_a2[wid] = g_dinv[wid] * (acc + g_at[wid]);
    if (lane == 1) g_cnt[wid] = 0;     // self-clean for next replay
}

// ============================ weightless aggregation ============================
// G[c] = sum_{e->c} X[src_e] + X[c]
// MODE 0: fp16 out (dinv²);  MODE 1: FINAL — fp32 out = dinv·G + a2·c4 + a1·e4 + f4
// FIRST: lane0 finalizes a1/at from g_pack low bits (pass 1 only).
// Tail + self handled by ONE predicated 8-slot batch (full MLP).
template <int MODE, bool FIRST>
__global__ void __launch_bounds__(256) k_aggp(const __half* __restrict__ X,
                                              void* __restrict__ Yv, int n) {
    int wid  = (blockIdx.x * blockDim.x + threadIdx.x) >> 5;
    int lane = threadIdx.x & 31;
    if (wid >= n) return;

    const int f0 = lane * 2;
    int e = g_off[wid];
    const int end = g_off[wid + 1];
    float a0 = 0.f, a1v = 0.f;

#define GATH(SRC) { __half2 h = *reinterpret_cast<const __half2*>(X + (size_t)(SRC) * 64 + f0); \
                    float2 f = __half22float2(h); a0 += f.x; a1v += f.y; }

    for (; e + 8 <= end; e += 8) {
        int s0 = g_src[e+0], s1 = g_src[e+1], s2 = g_src[e+2], s3 = g_src[e+3];
        int s4 = g_src[e+4], s5 = g_src[e+5], s6 = g_src[e+6], s7 = g_src[e+7];
        GATH(s0) GATH(s1) GATH(s2) GATH(s3) GATH(s4) GATH(s5) GATH(s6) GATH(s7)
    }
#undef GATH
    {   // predicated final batch: rem (=end-e, 0..7) edges + self = rem+1 slots of 8
        const int rem = end - e;
        int   idx[8];
        float wgt[8];
#pragma unroll
        for (int k = 0; k < 8; k++) {
            idx[k] = (k < rem) ? g_src[e + k] : wid;
            wgt[k] = (k <= rem) ? 1.f : 0.f;    // k<rem: edge; k==rem: self; else zero
        }
#pragma unroll
        for (int k = 0; k < 8; k++) {
            __half2 h = *reinterpret_cast<const __half2*>(X + (size_t)idx[k] * 64 + f0);
            float2 f = __half22float2(h);
            a0  += wgt[k] * f.x;
            a1v += wgt[k] * f.y;
        }
    }

    float dn = g_dinv[wid];
    if (FIRST && lane == 0) {
        unsigned low = (unsigned)g_pack[wid];                 // fixedpoint sum of dinv[src]
        float a1 = dn * ((float)low * (1.0f / FIXP) + dn);
        g_a1[wid] = a1;
        g_at[wid] = dn * a1;
    }
    if (MODE == 0) {
        float s = dn * dn;
        __half2 h = __floats2half2_rn(a0 * s, a1v * s);
        *reinterpret_cast<__half2*>((__half*)Yv + (size_t)wid * 64 + f0) = h;
    } else {
        float av1 = g_a1[wid], av2 = g_a2[wid];
        float2 c4v = *reinterpret_cast<const float2*>(g_c4 + f0);
        float2 e4v = *reinterpret_cast<const float2*>(g_e4 + f0);
        float2 f4v = *reinterpret_cast<const float2*>(g_f4 + f0);
        float2 o;
        o.x = a0  * dn + av2 * c4v.x + av1 * e4v.x + f4v.x;
        o.y = a1v * dn + av2 * c4v.y + av1 * e4v.y + f4v.y;
        *reinterpret_cast<float2*>((float*)Yv + (size_t)wid * 64 + f0) = o;
    }
}

// ============================ launch ============================

extern "C" void kernel_launch(void* const* d_in, const int* in_sizes, int n_in,
                              void* d_out, int out_size) {
    const float* latent = (const float*)d_in[0];
    const float* cond   = (const float*)d_in[1];
    const int*   edge   = (const int*)  d_in[2];
    const float* W1 = (const float*)d_in[3];
    const float* b1 = (const float*)d_in[4];
    const float* W2 = (const float*)d_in[5];
    const float* b2 = (const float*)d_in[6];
    const float* W3 = (const float*)d_in[7];
    const float* b3 = (const float*)d_in[8];
    const float* W4 = (const float*)d_in[9];
    const float* b4 = (const float*)d_in[10];

    const int n = in_sizes[0] / 64;      // 100000
    const int E = in_sizes[2] / 2;       // 1600000
    const int* row = edge;
    const int* col = edge + E;

    static __half *pT0 = nullptr, *pT1 = nullptr, *pT2 = nullptr;
    static cudaStream_t sB = nullptr;
    static cudaEvent_t ev0 = nullptr, evAdd = nullptr, evScale = nullptr,
                       evAgg1 = nullptr, evA2 = nullptr;
    if (!pT0) {
        cudaGetSymbolAddress((void**)&pT0, g_T0);
        cudaGetSymbolAddress((void**)&pT1, g_T1);
        cudaGetSymbolAddress((void**)&pT2, g_T2);
        cudaStreamCreateWithFlags(&sB, cudaStreamNonBlocking);
        cudaEventCreateWithFlags(&ev0,     cudaEventDisableTiming);
        cudaEventCreateWithFlags(&evAdd,   cudaEventDisableTiming);
        cudaEventCreateWithFlags(&evScale, cudaEventDisableTiming);
        cudaEventCreateWithFlags(&evAgg1,  cudaEventDisableTiming);
        cudaEventCreateWithFlags(&evA2,    cudaEventDisableTiming);
    }

    const int TB  = 256;
    const int gN  = (n + TB - 1) / TB;
    const int gE  = (E + TB - 1) / TB;
    const int gE4 = ((E + 3) / 4 + TB - 1) / TB;   // hist: 4 edges/thread
    const int nbS = (n + 1023) / 1024;             // <= 98 <= 128
    const int gN1 = (n + 1 + TB - 1) / TB;
    const int gW  = (n + 7) / 8;                   // warp per node, 8 warps/block
    const int gS  = (n * 8 + TB - 1) / TB;         // scale kernel

    // ---- fork: side stream B computes the weight path ----
    cudaEventRecord(ev0, 0);
    cudaStreamWaitEvent(sB, ev0, 0);
    k_wprep_a<<<24, 256, 0, sB>>>(W1, W2, W3);
    k_wprep_b<<<25, 256, 0, sB>>>(W3, W4, b1, b2, b3, b4);
    k_gemm0v<<<gN, TB, 0, sB>>>(latent, cond, n);   // Z = [L|C]@U2 (unscaled)

    // ---- main stream: edge/build chain ----
    k_hist<<<gE4, TB>>>(col, E);
    k_scan_local<<<nbS, 1024>>>(n);
    k_scan_add<<<gN1, TB>>>(n, E, nbS);
    cudaEventRecord(evAdd, 0);
    k_fill<<<gE, TB>>>(row, col, E);

    // ---- side stream: scale T0 by dinv (needs scan_add + gemm0v), overlaps fill ----
    cudaStreamWaitEvent(sB, evAdd, 0);
    k_scale<<<gS, TB, 0, sB>>>(n);
    cudaEventRecord(evScale, sB);

    // ---- main stream: agg1 (finalizes a1/at), agg2 ----
    cudaStreamWaitEvent(0, evScale, 0);
    k_aggp<0, true ><<<gW, TB>>>(pT0, pT1, n);
    cudaEventRecord(evAgg1, 0);
    k_aggp<0, false><<<gW, TB>>>(pT1, pT2, n);

    // ---- side stream: a2 gather (needs agg1's a1/at), overlaps agg2 ----
    cudaStreamWaitEvent(sB, evAgg1, 0);
    k_a2<<<gW, TB, 0, sB>>>(n);
    cudaEventRecord(evA2, sB);

    // ---- final agg writes out = P³Z·(folded W4) + a2·c4 + a1·e4 + f4 ----
    cudaStreamWaitEvent(0, evA2, 0);
    k_aggp<1, false><<<gW, TB>>>(pT2, (float*)d_out, n);
}

// round 15
// speedup vs baseline: 1.1803x; 1.0003x over previous
#include <cuda_runtime.h>
#include <cuda_fp16.h>

// ===== static scratch (allocation-free rule: __device__ globals) =====
#define N_MAX 100352
#define E_MAX 1700032

__device__ int                g_cnt[N_MAX];    // zero at load; self-cleaned by k_a2
__device__ unsigned long long g_pack[N_MAX];   // (cursor<<32)|fixedpoint dinv-sum
__device__ int   g_off[N_MAX + 1];
__device__ int   g_bsum[128];
__device__ int   g_scanflag;                   // publish counter; self-cleaned by k_a2
__device__ float g_dinv[N_MAX];
__device__ int   g_src[E_MAX];

__device__ float g_a1[N_MAX];        // P·1
__device__ float g_at[N_MAX];        // dinv * a1
__device__ float g_a2[N_MAX];        // P²·1
__device__ float g_U [96 * 64];      // [W1@W3_top ; W2@W3_bot]
__device__ float g_U2[96 * 64];      // U @ W4
__device__ float g_c4[64];
__device__ float g_e4[64];
__device__ float g_f4[64];

__device__ __align__(16) __half g_T0[(size_t)N_MAX * 64];  // Dinv·([L|C]@U2)
__device__ __align__(16) __half g_T1[(size_t)N_MAX * 64];
__device__ __align__(16) __half g_T2[(size_t)N_MAX * 64];

#define FIXP 16777216.0f   // 2^24

// ===== packed fp32x2 helpers (sm_103a) =====
__device__ __forceinline__ unsigned long long ffma2(unsigned long long a,
                                                    unsigned long long b,
                                                    unsigned long long c) {
    unsigned long long d;
    asm("fma.rn.f32x2 %0, %1, %2, %3;" : "=l"(d) : "l"(a), "l"(b), "l"(c));
    return d;
}
__device__ __forceinline__ unsigned long long pack2(float x) {
    unsigned long long d;
    asm("mov.b64 %0, {%1, %1};" : "=l"(d) : "r"(__float_as_uint(x)));
    return d;
}
__device__ __forceinline__ float2 unpack2(unsigned long long v) {
    unsigned int lo, hi;
    asm("mov.b64 {%0, %1}, %2;" : "=r"(lo), "=r"(hi) : "l"(v));
    return make_float2(__uint_as_float(lo), __uint_as_float(hi));
}

// ============================ graph construction ============================

// 4 edges per thread for MLP on the atomics
__global__ void k_hist(const int* __restrict__ col, int E) {
    int e = (blockIdx.x * blockDim.x + threadIdx.x) * 4;
    if (e + 4 <= E) {
        int4 c = *reinterpret_cast<const int4*>(col + e);
        atomicAdd(&g_cnt[c.x], 1);
        atomicAdd(&g_cnt[c.y], 1);
        atomicAdd(&g_cnt[c.z], 1);
        atomicAdd(&g_cnt[c.w], 1);
    } else {
        for (; e < E; e++) atomicAdd(&g_cnt[col[e]], 1);
    }
}

// single-kernel scan: local scan + publish + spin + finalize (98 blocks co-resident on 148 SMs)
__global__ void __launch_bounds__(1024) k_scan(int n, int E) {
    __shared__ int s[1024];
    __shared__ int sPre;
    int tid = threadIdx.x;
    int b = blockIdx.x;
    int i = b * 1024 + tid;
    int v = (i < n) ? g_cnt[i] : 0;
    s[tid] = v;
    __syncthreads();
    for (int d = 1; d < 1024; d <<= 1) {
        int t = (tid >= d) ? s[tid - d] : 0;
        __syncthreads();
        s[tid] += t;                      // inclusive scan
        __syncthreads();
    }
    if (tid == 1023) {
        g_bsum[b] = s[1023];
        __threadfence();
        atomicAdd(&g_scanflag, 1);
    }
    if (tid == 0) {
        while (atomicAdd(&g_scanflag, 0) < (int)gridDim.x) { }
        __threadfence();
        int p = 0;
        for (int j = 0; j < b; j++) p += g_bsum[j];
        sPre = p;
    }
    __syncthreads();
    if (i < n) {
        int o = s[tid] - v + sPre;        // exclusive + block prefix
        g_off[i]  = o;
        g_pack[i] = (unsigned long long)(unsigned)o << 32;
        g_dinv[i] = rsqrtf((float)(v + 1));
    }
    if (i == n) g_off[n] = E;
}

// fill CSR src: ONE packed 64-bit atomic per edge; 2 edges/thread for MLP
__global__ void k_fill(const int* __restrict__ row, const int* __restrict__ col, int E) {
    int e = (blockIdx.x * blockDim.x + threadIdx.x) * 2;
    if (e + 2 <= E) {
        int2 r = *reinterpret_cast<const int2*>(row + e);
        int2 c = *reinterpret_cast<const int2*>(col + e);
        unsigned q0 = (unsigned)__float2uint_rn(g_dinv[r.x] * FIXP);
        unsigned q1 = (unsigned)__float2uint_rn(g_dinv[r.y] * FIXP);
        unsigned long long t0 =
            atomicAdd(&g_pack[c.x], ((unsigned long long)1 << 32) | (unsigned long long)q0);
        unsigned long long t1 =
            atomicAdd(&g_pack[c.y], ((unsigned long long)1 << 32) | (unsigned long long)q1);
        g_src[(int)(t0 >> 32)] = r.x;
        g_src[(int)(t1 >> 32)] = r.y;
    } else {
        for (; e < E; e++) {
            int r = row[e], c = col[e];
            unsigned q = (unsigned)__float2uint_rn(g_dinv[r] * FIXP);
            unsigned long long ret =
                atomicAdd(&g_pack[c], ((unsigned long long)1 << 32) | (unsigned long long)q);
            g_src[(int)(ret >> 32)] = r;
        }
    }
}

// ============================ weight precompute (side stream) ============================
__global__ void __launch_bounds__(256) k_wprep_a(
        const float* __restrict__ W1, const float* __restrict__ W2,
        const float* __restrict__ W3) {
    __shared__ float sB[64 * 64];
    __shared__ float sA[4 * 64];
    int tid = threadIdx.x;
    int k0 = blockIdx.x * 4;
    int half = (k0 >= 64);
    const float* Wsrc = W3 + (size_t)half * 64 * 64;
    for (int i = tid; i < 64 * 64; i += 256) sB[i] = Wsrc[i];
    const float* Arow = half ? (W2 + (size_t)(k0 - 64) * 64) : (W1 + (size_t)k0 * 64);
    sA[tid] = Arow[tid];
    __syncthreads();
    int k = tid >> 6, j = tid & 63;
    float s = 0.f;
#pragma unroll
    for (int m = 0; m < 64; m++) s += sA[k * 64 + m] * sB[m * 64 + j];
    g_U[(k0 + k) * 64 + j] = s;
}

__global__ void __launch_bounds__(256) k_wprep_b(
        const float* __restrict__ W3, const float* __restrict__ W4,
        const float* __restrict__ b1, const float* __restrict__ b2,
        const float* __restrict__ b3, const float* __restrict__ b4) {
    int tid = threadIdx.x;
    int b = blockIdx.x;
    if (b < 24) {
        __shared__ float sB[64 * 64];
        __shared__ float sA[4 * 64];
        int k0 = b * 4;
        for (int i = tid; i < 64 * 64; i += 256) sB[i] = W4[i];
        sA[tid] = g_U[(size_t)k0 * 64 + tid];
        __syncthreads();
        int k = tid >> 6, j = tid & 63;
        float s = 0.f;
#pragma unroll
        for (int m = 0; m < 64; m++) s += sA[k * 64 + m] * sB[m * 64 + j];
        g_U2[(k0 + k) * 64 + j] = s;
    } else {
        __shared__ float c3[64];
        int j = tid & 63;
        if (tid < 64) {
            float s = 0.f;
            for (int m = 0; m < 128; m++)
                s += ((m < 64) ? b1[m] : b2[m - 64]) * W3[m * 64 + j];
            c3[j] = s;
        }
        __syncthreads();
        if (tid < 64) {
            float s = 0.f, t = 0.f;
            for (int m = 0; m < 64; m++) {
                s += c3[m] * W4[m * 64 + j];
                t += b3[m] * W4[m * 64 + j];
            }
            g_c4[j] = s; g_e4[j] = t; g_f4[j] = b4[j];
        }
    }
}

// ============================ gemm0s: T0 = Dinv·([L|C]@U2) (scale folded in) ============================
__global__ void __launch_bounds__(256) k_gemm0s(const float* __restrict__ latent,
                                                const float* __restrict__ cond, int n) {
    __shared__ __align__(16) float sW[96 * 64];
    for (int i = threadIdx.x; i < 96 * 64; i += blockDim.x) sW[i] = g_U2[i];
    __syncthreads();
    int node = blockIdx.x * blockDim.x + threadIdx.x;
    if (node >= n) return;

    unsigned long long acc[32];
#pragma unroll
    for (int j = 0; j < 32; j++) acc[j] = 0ull;

    const float* pL = latent + (size_t)node * 64;
    const float* pC = cond   + (size_t)node * 32;
#pragma unroll 2
    for (int k = 0; k < 96; k += 4) {
        float4 av = (k < 64) ? *reinterpret_cast<const float4*>(pL + k)
                             : *reinterpret_cast<const float4*>(pC + (k - 64));
        unsigned long long p0 = pack2(av.x), p1 = pack2(av.y);
        unsigned long long p2 = pack2(av.z), p3 = pack2(av.w);
        const ulonglong2* w0 = reinterpret_cast<const ulonglong2*>(sW + (k + 0) * 64);
        const ulonglong2* w1 = reinterpret_cast<const ulonglong2*>(sW + (k + 1) * 64);
        const ulonglong2* w2 = reinterpret_cast<const ulonglong2*>(sW + (k + 2) * 64);
        const ulonglong2* w3 = reinterpret_cast<const ulonglong2*>(sW + (k + 3) * 64);
#pragma unroll
        for (int j = 0; j < 16; j++) {
            ulonglong2 q;
            q = w0[j]; acc[2*j] = ffma2(p0, q.x, acc[2*j]); acc[2*j+1] = ffma2(p0, q.y, acc[2*j+1]);
            q = w1[j]; acc[2*j] = ffma2(p1, q.x, acc[2*j]); acc[2*j+1] = ffma2(p1, q.y, acc[2*j+1]);
            q = w2[j]; acc[2*j] = ffma2(p2, q.x, acc[2*j]); acc[2*j+1] = ffma2(p2, q.y, acc[2*j+1]);
            q = w3[j]; acc[2*j] = ffma2(p3, q.x, acc[2*j]); acc[2*j+1] = ffma2(p3, q.y, acc[2*j+1]);
        }
    }

    float dn = g_dinv[node];   // scan has completed (stream dependency)
    __half* yp = g_T0 + (size_t)node * 64;
#pragma unroll
    for (int j = 0; j < 8; j++) {
        float2 f0 = unpack2(acc[4*j+0]);
        float2 f1 = unpack2(acc[4*j+1]);
        float2 f2 = unpack2(acc[4*j+2]);
        float2 f3 = unpack2(acc[4*j+3]);
        __half2 h0 = __floats2half2_rn(f0.x * dn, f0.y * dn);
        __half2 h1 = __floats2half2_rn(f1.x * dn, f1.y * dn);
        __half2 h2 = __floats2half2_rn(f2.x * dn, f2.y * dn);
        __half2 h3 = __floats2half2_rn(f3.x * dn, f3.y * dn);
        uint4 u = make_uint4(*reinterpret_cast<unsigned*>(&h0), *reinterpret_cast<unsigned*>(&h1),
                             *reinterpret_cast<unsigned*>(&h2), *reinterpret_cast<unsigned*>(&h3));
        *reinterpret_cast<uint4*>(yp + 8 * j) = u;
    }
}

// a2 = P·a1 (side stream, overlaps agg2); self-cleans g_cnt + scanflag for next replay
__global__ void k_a2(int n) {
    int wid  = (blockIdx.x * blockDim.x + threadIdx.x) >> 5;
    int lane = threadIdx.x & 31;
    if (wid >= n) return;
    int beg = g_off[wid], end = g_off[wid + 1];
    float acc = 0.f;
    for (int e = beg + lane; e < end; e += 32) acc += g_at[g_src[e]];
    for (int d = 16; d; d >>= 1) acc += __shfl_down_sync(0xffffffffu, acc, d);
    if (lane == 0) g_a2[wid] = g_dinv[wid] * (acc + g_at[wid]);
    if (lane == 1) g_cnt[wid] = 0;
    if (lane == 2 && wid == 0) g_scanflag = 0;
}

// ============================ weightless aggregation (R14-proven) ============================
template <int MODE, bool FIRST>
__global__ void __launch_bounds__(256) k_aggp(const __half* __restrict__ X,
                                              void* __restrict__ Yv, int n) {
    int wid  = (blockIdx.x * blockDim.x + threadIdx.x) >> 5;
    int lane = threadIdx.x & 31;
    if (wid >= n) return;

    const int f0 = lane * 2;
    int e = g_off[wid];
    const int end = g_off[wid + 1];
    float a0 = 0.f, a1v = 0.f;

#define GATH(SRC) { __half2 h = *reinterpret_cast<const __half2*>(X + (size_t)(SRC) * 64 + f0); \
                    float2 f = __half22float2(h); a0 += f.x; a1v += f.y; }

    for (; e + 8 <= end; e += 8) {
        int s0 = g_src[e+0], s1 = g_src[e+1], s2 = g_src[e+2], s3 = g_src[e+3];
        int s4 = g_src[e+4], s5 = g_src[e+5], s6 = g_src[e+6], s7 = g_src[e+7];
        GATH(s0) GATH(s1) GATH(s2) GATH(s3) GATH(s4) GATH(s5) GATH(s6) GATH(s7)
    }
#undef GATH
    {   // predicated final batch: rem edges + self, always 8 slots (full MLP)
        const int rem = end - e;
        int   idx[8];
        float wgt[8];
#pragma unroll
        for (int k = 0; k < 8; k++) {
            idx[k] = (k < rem) ? g_src[e + k] : wid;
            wgt[k] = (k <= rem) ? 1.f : 0.f;
        }
#pragma unroll
        for (int k = 0; k < 8; k++) {
            __half2 h = *reinterpret_cast<const __half2*>(X + (size_t)idx[k] * 64 + f0);
            float2 f = __half22float2(h);
            a0  += wgt[k] * f.x;
            a1v += wgt[k] * f.y;
        }
    }

    float dn = g_dinv[wid];
    if (FIRST && lane == 0) {
        unsigned low = (unsigned)g_pack[wid];
        float a1 = dn * ((float)low * (1.0f / FIXP) + dn);
        g_a1[wid] = a1;
        g_at[wid] = dn * a1;
    }
    if (MODE == 0) {
        float s = dn * dn;
        __half2 h = __floats2half2_rn(a0 * s, a1v * s);
        *reinterpret_cast<__half2*>((__half*)Yv + (size_t)wid * 64 + f0) = h;
    } else {
        float av1 = g_a1[wid], av2 = g_a2[wid];
        float2 c4v = *reinterpret_cast<const float2*>(g_c4 + f0);
        float2 e4v = *reinterpret_cast<const float2*>(g_e4 + f0);
        float2 f4v = *reinterpret_cast<const float2*>(g_f4 + f0);
        float2 o;
        o.x = a0  * dn + av2 * c4v.x + av1 * e4v.x + f4v.x;
        o.y = a1v * dn + av2 * c4v.y + av1 * e4v.y + f4v.y;
        *reinterpret_cast<float2*>((float*)Yv + (size_t)wid * 64 + f0) = o;
    }
}

// ============================ launch ============================

extern "C" void kernel_launch(void* const* d_in, const int* in_sizes, int n_in,
                              void* d_out, int out_size) {
    const float* latent = (const float*)d_in[0];
    const float* cond   = (const float*)d_in[1];
    const int*   edge   = (const int*)  d_in[2];
    const float* W1 = (const float*)d_in[3];
    const float* b1 = (const float*)d_in[4];
    const float* W2 = (const float*)d_in[5];
    const float* b2 = (const float*)d_in[6];
    const float* W3 = (const float*)d_in[7];
    const float* b3 = (const float*)d_in[8];
    const float* W4 = (const float*)d_in[9];
    const float* b4 = (const float*)d_in[10];

    const int n = in_sizes[0] / 64;      // 100000
    const int E = in_sizes[2] / 2;       // 1600000
    const int* row = edge;
    const int* col = edge + E;

    static __half *pT0 = nullptr, *pT1 = nullptr, *pT2 = nullptr;
    static cudaStream_t sB = nullptr;
    static cudaEvent_t ev0 = nullptr, evAdd = nullptr, evG0 = nullptr,
                       evAgg1 = nullptr, evA2 = nullptr;
    if (!pT0) {
        cudaGetSymbolAddress((void**)&pT0, g_T0);
        cudaGetSymbolAddress((void**)&pT1, g_T1);
        cudaGetSymbolAddress((void**)&pT2, g_T2);
        cudaStreamCreateWithFlags(&sB, cudaStreamNonBlocking);
        cudaEventCreateWithFlags(&ev0,    cudaEventDisableTiming);
        cudaEventCreateWithFlags(&evAdd,  cudaEventDisableTiming);
        cudaEventCreateWithFlags(&evG0,   cudaEventDisableTiming);
        cudaEventCreateWithFlags(&evAgg1, cudaEventDisableTiming);
        cudaEventCreateWithFlags(&evA2,   cudaEventDisableTiming);
    }

    const int TB  = 256;
    const int gN  = (n + TB - 1) / TB;
    const int gE2 = ((E + 1) / 2 + TB - 1) / TB;   // fill: 2 edges/thread
    const int gE4 = ((E + 3) / 4 + TB - 1) / TB;   // hist: 4 edges/thread
    const int nbS = (n + 1023) / 1024;             // 98 blocks (co-resident)
    const int gW  = (n + 7) / 8;                   // warp per node

    // ---- fork: side stream B computes weights ----
    cudaEventRecord(ev0, 0);
    cudaStreamWaitEvent(sB, ev0, 0);
    k_wprep_a<<<24, 256, 0, sB>>>(W1, W2, W3);
    k_wprep_b<<<25, 256, 0, sB>>>(W3, W4, b1, b2, b3, b4);

    // ---- main stream: hist + fused scan ----
    k_hist<<<gE4, TB>>>(col, E);
    k_scan<<<nbS, 1024>>>(n, E);
    cudaEventRecord(evAdd, 0);
    k_fill<<<gE2, TB>>>(row, col, E);

    // ---- side stream: gemm0s (scale folded; needs dinv from scan), overlaps fill ----
    cudaStreamWaitEvent(sB, evAdd, 0);
    k_gemm0s<<<gN, TB, 0, sB>>>(latent, cond, n);
    cudaEventRecord(evG0, sB);

    // ---- main stream: agg1 (finalizes a1/at), agg2 ----
    cudaStreamWaitEvent(0, evG0, 0);
    k_aggp<0, true ><<<gW, TB>>>(pT0, pT1, n);
    cudaEventRecord(evAgg1, 0);
    k_aggp<0, false><<<gW, TB>>>(pT1, pT2, n);

    // ---- side stream: a2 (needs agg1's a1/at), overlaps agg2 ----
    cudaStreamWaitEvent(sB, evAgg1, 0);
    k_a2<<<gW, TB, 0, sB>>>(n);
    cudaEventRecord(evA2, sB);

    // ---- final agg writes out = P³Z(+folded W4) + a2·c4 + a1·e4 + f4 ----
    cudaStreamWaitEvent(0, evA2, 0);
    k_aggp<1, false><<<gW, TB>>>(pT2, (float*)d_out, n);
}